// round 1
// baseline (speedup 1.0000x reference)
#include <cuda_runtime.h>
#include <math.h>

#define Bn    2
#define Sn    2048
#define DIN   2048
#define Hn    16
#define Gn    4
#define HD    128
#define DOUT  2048
#define GROUPn 4          // H / G
#define EPSf  1e-6f

// ---------------- scratch (device globals; no allocation allowed) ----------
__device__ float g_QG  [(size_t)Bn*Sn*Hn*2*HD];   // [b,s,h,2*HD]  (q | gate)
__device__ float g_Kraw[(size_t)Bn*Sn*Gn*HD];     // [b,s,g,HD]
__device__ float g_Vraw[(size_t)Bn*Sn*Gn*HD];     // [b,s,g,HD]
__device__ float g_Q   [(size_t)Bn*Hn*Sn*HD];     // [b,h,s,HD]  normed+roped
__device__ float g_K   [(size_t)Bn*Gn*Sn*HD];     // [b,g,s,HD]  normed+roped
__device__ float g_V   [(size_t)Bn*Gn*Sn*HD];     // [b,g,s,HD]
__device__ float g_Ctx [(size_t)Bn*Sn*DOUT];      // [b,s,h*HD]  gated context

// ---------------- generic fp32 SGEMM: C[M,N] = A[M,K] @ B[K,N] -------------
// 128x128 tile, BK=8, 256 threads, 8x8 per thread. M,N % 128 == 0, K % 8 == 0.
__global__ __launch_bounds__(256) void sgemm128(
    const float* __restrict__ A, const float* __restrict__ Bm,
    float* __restrict__ C, int M, int N, int K)
{
    __shared__ float As[8][128];
    __shared__ float Bs[8][128];
    const int tid  = threadIdx.x;
    const int brow = blockIdx.y * 128;
    const int bcol = blockIdx.x * 128;
    const int tr   = (tid / 16) * 8;
    const int tc   = (tid % 16) * 8;

    const int arow = tid >> 1;           // 0..127
    const int acol = (tid & 1) * 4;      // 0 or 4
    const int bkr  = tid >> 5;           // 0..7
    const int bcc  = (tid & 31) * 4;     // 0..124

    float acc[8][8];
    #pragma unroll
    for (int i = 0; i < 8; i++)
        #pragma unroll
        for (int j = 0; j < 8; j++) acc[i][j] = 0.f;

    for (int kk = 0; kk < K; kk += 8) {
        float4 a4 = *(const float4*)(A + (size_t)(brow + arow) * K + kk + acol);
        As[acol + 0][arow] = a4.x;
        As[acol + 1][arow] = a4.y;
        As[acol + 2][arow] = a4.z;
        As[acol + 3][arow] = a4.w;
        float4 b4 = *(const float4*)(Bm + (size_t)(kk + bkr) * N + bcol + bcc);
        *(float4*)&Bs[bkr][bcc] = b4;
        __syncthreads();
        #pragma unroll
        for (int k = 0; k < 8; ++k) {
            float a[8], b[8];
            #pragma unroll
            for (int i = 0; i < 8; i++) a[i] = As[k][tr + i];
            #pragma unroll
            for (int j = 0; j < 8; j++) b[j] = Bs[k][tc + j];
            #pragma unroll
            for (int i = 0; i < 8; i++)
                #pragma unroll
                for (int j = 0; j < 8; j++) acc[i][j] = fmaf(a[i], b[j], acc[i][j]);
        }
        __syncthreads();
    }
    #pragma unroll
    for (int i = 0; i < 8; i++)
        #pragma unroll
        for (int j = 0; j < 8; j += 4) {
            float4 v = make_float4(acc[i][j], acc[i][j+1], acc[i][j+2], acc[i][j+3]);
            *(float4*)(C + (size_t)(brow + tr + i) * N + bcol + tc + j) = v;
        }
}

// ---------------- rmsnorm + rope for Q (one block per (b,s,h)) -------------
__global__ __launch_bounds__(128) void qnorm_rope(
    const float* __restrict__ QG, const float* __restrict__ w,
    const float* __restrict__ cosT, const float* __restrict__ sinT,
    float* __restrict__ Qo)
{
    const int s = blockIdx.x, h = blockIdx.y, b = blockIdx.z;
    const int d = threadIdx.x;
    const float* src = QG + (((size_t)(b * Sn + s) * Hn + h) * 2 * HD);
    float x = src[d];
    float ss = x * x;
    #pragma unroll
    for (int o = 16; o > 0; o >>= 1) ss += __shfl_xor_sync(0xffffffffu, ss, o);
    __shared__ float wsum[4];
    if ((d & 31) == 0) wsum[d >> 5] = ss;
    __syncthreads();
    float tot = wsum[0] + wsum[1] + wsum[2] + wsum[3];
    float inv = rsqrtf(tot * (1.0f / HD) + EPSf);
    float n = x * inv * (1.0f + w[d]);
    __shared__ float nb[HD];
    nb[d] = n;
    __syncthreads();
    float c  = cosT[(size_t)s * HD + d];
    float sn = sinT[(size_t)s * HD + d];
    float rot = (d < HD / 2) ? -nb[d + HD / 2] : nb[d - HD / 2];
    Qo[((size_t)(b * Hn + h) * Sn + s) * HD + d] = n * c + rot * sn;
}

// ---------------- rmsnorm + rope for K, plus V transpose -------------------
__global__ __launch_bounds__(128) void knorm_rope_vcopy(
    const float* __restrict__ Kraw, const float* __restrict__ Vraw,
    const float* __restrict__ w,
    const float* __restrict__ cosT, const float* __restrict__ sinT,
    float* __restrict__ Ko, float* __restrict__ Vo)
{
    const int s = blockIdx.x, g = blockIdx.y, b = blockIdx.z;
    const int d = threadIdx.x;
    const size_t src = ((size_t)(b * Sn + s) * Gn + g) * HD + d;
    float x = Kraw[src];
    float ss = x * x;
    #pragma unroll
    for (int o = 16; o > 0; o >>= 1) ss += __shfl_xor_sync(0xffffffffu, ss, o);
    __shared__ float wsum[4];
    if ((d & 31) == 0) wsum[d >> 5] = ss;
    __syncthreads();
    float tot = wsum[0] + wsum[1] + wsum[2] + wsum[3];
    float inv = rsqrtf(tot * (1.0f / HD) + EPSf);
    float n = x * inv * (1.0f + w[d]);
    __shared__ float nb[HD];
    nb[d] = n;
    __syncthreads();
    float c  = cosT[(size_t)s * HD + d];
    float sn = sinT[(size_t)s * HD + d];
    float rot = (d < HD / 2) ? -nb[d + HD / 2] : nb[d - HD / 2];
    const size_t dst = ((size_t)(b * Gn + g) * Sn + s) * HD + d;
    Ko[dst] = n * c + rot * sn;
    Vo[dst] = Vraw[src];
}

// ---------------- causal flash attention + sigmoid gate --------------------
#define BQ 64
#define BK 64
// smem floats: Qs 64*128 + Kst 128*64 + Vs 64*128 + Ss 64*64 + 3*64
#define ATTN_SMEM_FLOATS (BQ*HD + HD*BK + BK*HD + BQ*BK + 3*BQ)

__global__ __launch_bounds__(256) void attn_kernel(
    const float* __restrict__ Q, const float* __restrict__ Kt,
    const float* __restrict__ Vt, const float* __restrict__ QG,
    float* __restrict__ Ctx)
{
    extern __shared__ float sm[];
    float* Qs  = sm;                    // [BQ][HD]
    float* Kst = Qs  + BQ * HD;         // [HD][BK]   (transposed)
    float* Vs  = Kst + HD * BK;         // [BK][HD]
    float* Ss  = Vs  + BK * HD;         // [BQ][BK]
    float* Ms  = Ss  + BQ * BK;
    float* Ls  = Ms  + BQ;
    float* Fs  = Ls  + BQ;

    const int qi = blockIdx.x, h = blockIdx.y, b = blockIdx.z;
    const int g  = h / GROUPn;
    const int tid = threadIdx.x;
    const int r0  = (tid / 16) * 4;     // 4 q-rows per thread
    const int kc0 = (tid % 16) * 4;     // 4 k-cols (score phase)
    const int c0  = (tid % 16) * 8;     // 8 d-cols (PV phase)
    const float scale = 0.08838834764831845f; // 1/sqrt(128)

    const float* Qbase = Q  + ((size_t)(b * Hn + h) * Sn + (size_t)qi * BQ) * HD;
    const float* Kbase = Kt + ((size_t)(b * Gn + g) * Sn) * HD;
    const float* Vbase = Vt + ((size_t)(b * Gn + g) * Sn) * HD;

    for (int i = tid * 4; i < BQ * HD; i += 1024)
        *(float4*)&Qs[i] = *(const float4*)&Qbase[i];
    if (tid < BQ) { Ms[tid] = -INFINITY; Ls[tid] = 0.f; }

    float acc[4][8];
    #pragma unroll
    for (int i = 0; i < 4; i++)
        #pragma unroll
        for (int j = 0; j < 8; j++) acc[i][j] = 0.f;

    const int ntiles = qi + 1;
    for (int t = 0; t < ntiles; ++t) {
        __syncthreads();  // protect Ss/Vs/Kst reads of previous iter
        const float* kp = Kbase + (size_t)t * BK * HD;
        const float* vp = Vbase + (size_t)t * BK * HD;
        for (int i = tid * 4; i < BK * HD; i += 1024) {
            int k = i / HD, d = i % HD;
            float4 kv = *(const float4*)&kp[i];
            Kst[(d + 0) * BK + k] = kv.x;
            Kst[(d + 1) * BK + k] = kv.y;
            Kst[(d + 2) * BK + k] = kv.z;
            Kst[(d + 3) * BK + k] = kv.w;
            *(float4*)&Vs[i] = *(const float4*)&vp[i];
        }
        __syncthreads();

        // scores: 4x4 register tile
        float sreg[4][4];
        #pragma unroll
        for (int i = 0; i < 4; i++)
            #pragma unroll
            for (int j = 0; j < 4; j++) sreg[i][j] = 0.f;
        #pragma unroll 4
        for (int d = 0; d < HD; ++d) {
            float4 k4 = *(const float4*)&Kst[d * BK + kc0];
            float kv[4] = {k4.x, k4.y, k4.z, k4.w};
            #pragma unroll
            for (int i = 0; i < 4; i++) {
                float qv = Qs[(r0 + i) * HD + d];
                #pragma unroll
                for (int j = 0; j < 4; j++) sreg[i][j] = fmaf(qv, kv[j], sreg[i][j]);
            }
        }
        const bool diag = (t == qi);
        #pragma unroll
        for (int i = 0; i < 4; i++)
            #pragma unroll
            for (int j = 0; j < 4; j++) {
                float v = sreg[i][j] * scale;
                if (diag && (kc0 + j > r0 + i)) v = -INFINITY;
                Ss[(r0 + i) * BK + kc0 + j] = v;
            }
        __syncthreads();

        // online softmax row pass (one thread per q-row)
        if (tid < BQ) {
            const int r = tid;
            float m_old = Ms[r];
            float mt = m_old;
            #pragma unroll 8
            for (int k = 0; k < BK; ++k) mt = fmaxf(mt, Ss[r * BK + k]);
            float f = expf(m_old - mt);
            float l = Ls[r] * f;
            #pragma unroll 8
            for (int k = 0; k < BK; ++k) {
                float p = expf(Ss[r * BK + k] - mt);
                Ss[r * BK + k] = p;
                l += p;
            }
            Ms[r] = mt; Ls[r] = l; Fs[r] = f;
        }
        __syncthreads();

        // rescale + PV
        #pragma unroll
        for (int i = 0; i < 4; i++) {
            float f = Fs[r0 + i];
            #pragma unroll
            for (int j = 0; j < 8; j++) acc[i][j] *= f;
        }
        #pragma unroll 2
        for (int kk = 0; kk < BK; ++kk) {
            float4 va = *(const float4*)&Vs[kk * HD + c0];
            float4 vb = *(const float4*)&Vs[kk * HD + c0 + 4];
            #pragma unroll
            for (int i = 0; i < 4; i++) {
                float p = Ss[(r0 + i) * BK + kk];
                acc[i][0] = fmaf(p, va.x, acc[i][0]);
                acc[i][1] = fmaf(p, va.y, acc[i][1]);
                acc[i][2] = fmaf(p, va.z, acc[i][2]);
                acc[i][3] = fmaf(p, va.w, acc[i][3]);
                acc[i][4] = fmaf(p, vb.x, acc[i][4]);
                acc[i][5] = fmaf(p, vb.y, acc[i][5]);
                acc[i][6] = fmaf(p, vb.z, acc[i][6]);
                acc[i][7] = fmaf(p, vb.w, acc[i][7]);
            }
        }
    }

    // epilogue: /l, * sigmoid(gate), write [b,s,h*HD+c]
    #pragma unroll
    for (int i = 0; i < 4; i++) {
        const int q = qi * BQ + r0 + i;
        const float invl = 1.0f / Ls[r0 + i];
        const float* gp = QG + (((size_t)(b * Sn + q) * Hn + h) * 2 * HD) + HD + c0;
        float* cp = Ctx + (size_t)(b * Sn + q) * DOUT + h * HD + c0;
        #pragma unroll
        for (int j = 0; j < 8; j++) {
            float gate = gp[j];
            float sig = 1.0f / (1.0f + expf(-gate));
            cp[j] = acc[i][j] * invl * sig;
        }
    }
}

// ---------------------------- launcher -------------------------------------
extern "C" void kernel_launch(void* const* d_in, const int* in_sizes, int n_in,
                              void* d_out, int out_size)
{
    const float* x    = (const float*)d_in[0];
    const float* Wq   = (const float*)d_in[1];
    const float* Wk   = (const float*)d_in[2];
    const float* Wv   = (const float*)d_in[3];
    const float* Wo   = (const float*)d_in[4];
    const float* qw   = (const float*)d_in[5];
    const float* kw   = (const float*)d_in[6];
    const float* cosT = (const float*)d_in[7];
    const float* sinT = (const float*)d_in[8];
    float* out = (float*)d_out;

    float *QG, *Kraw, *Vraw, *Qb, *Kb, *Vb, *Ctx;
    cudaGetSymbolAddress((void**)&QG,   g_QG);
    cudaGetSymbolAddress((void**)&Kraw, g_Kraw);
    cudaGetSymbolAddress((void**)&Vraw, g_Vraw);
    cudaGetSymbolAddress((void**)&Qb,   g_Q);
    cudaGetSymbolAddress((void**)&Kb,   g_K);
    cudaGetSymbolAddress((void**)&Vb,   g_V);
    cudaGetSymbolAddress((void**)&Ctx,  g_Ctx);

    const size_t attn_smem = ATTN_SMEM_FLOATS * sizeof(float);
    cudaFuncSetAttribute(attn_kernel, cudaFuncAttributeMaxDynamicSharedMemorySize,
                         (int)attn_smem);

    const int M = Bn * Sn;  // 4096

    // QKV projections
    sgemm128<<<dim3((2 * DOUT) / 128, M / 128), 256>>>(x, Wq, QG,  M, 2 * DOUT, DIN);
    sgemm128<<<dim3((Gn * HD) / 128, M / 128), 256>>>(x, Wk, Kraw, M, Gn * HD, DIN);
    sgemm128<<<dim3((Gn * HD) / 128, M / 128), 256>>>(x, Wv, Vraw, M, Gn * HD, DIN);

    // norm + rope (+ V transpose)
    qnorm_rope<<<dim3(Sn, Hn, Bn), 128>>>(QG, qw, cosT, sinT, Qb);
    knorm_rope_vcopy<<<dim3(Sn, Gn, Bn), 128>>>(Kraw, Vraw, kw, cosT, sinT, Kb, Vb);

    // causal attention + gate
    attn_kernel<<<dim3(Sn / BQ, Hn, Bn), 256, attn_smem>>>(Qb, Kb, Vb, QG, Ctx);

    // output projection
    sgemm128<<<dim3(DIN / 128, M / 128), 256>>>(Ctx, Wo, out, M, DIN, DOUT);
}

// round 3
// speedup vs baseline: 1.5291x; 1.5291x over previous
#include <cuda_runtime.h>
#include <cuda_bf16.h>
#include <math.h>
#include <stdint.h>

#define Bn    2
#define Sn    2048
#define DIN   2048
#define Hn    16
#define Gn    4
#define HD    128
#define DOUT  2048
#define GROUPn 4          // H / G
#define EPSf  1e-6f
#define Mrows (Bn*Sn)     // 4096

// ---------------- scratch (device globals; no allocation allowed) ----------
__device__ float g_QG  [(size_t)Bn*Sn*Hn*2*HD];   // [b,s,h,2*HD]  (q | gate)
__device__ float g_Kraw[(size_t)Bn*Sn*Gn*HD];     // [b,s,g,HD]
__device__ float g_Vraw[(size_t)Bn*Sn*Gn*HD];     // [b,s,g,HD]
__device__ float g_Q   [(size_t)Bn*Hn*Sn*HD];     // [b,h,s,HD]  normed+roped
__device__ float g_K   [(size_t)Bn*Gn*Sn*HD];     // [b,g,s,HD]  normed+roped
__device__ float g_V   [(size_t)Bn*Gn*Sn*HD];     // [b,g,s,HD]
__device__ float g_Ctx [(size_t)Bn*Sn*DOUT];      // [b,s,h*HD]  gated context

// bf16 split scratch
__device__ __nv_bfloat16 g_xh [(size_t)Mrows*DIN];
__device__ __nv_bfloat16 g_xl [(size_t)Mrows*DIN];
__device__ __nv_bfloat16 g_Wqh[(size_t)(2*DOUT)*DIN];   // [N=4096][K=2048]
__device__ __nv_bfloat16 g_Wql[(size_t)(2*DOUT)*DIN];
__device__ __nv_bfloat16 g_Wkh[(size_t)(Gn*HD)*DIN];    // [512][2048]
__device__ __nv_bfloat16 g_Wkl[(size_t)(Gn*HD)*DIN];
__device__ __nv_bfloat16 g_Wvh[(size_t)(Gn*HD)*DIN];
__device__ __nv_bfloat16 g_Wvl[(size_t)(Gn*HD)*DIN];
__device__ __nv_bfloat16 g_Woh[(size_t)DIN*DOUT];       // [N=2048][K=2048]
__device__ __nv_bfloat16 g_Wol[(size_t)DIN*DOUT];
__device__ __nv_bfloat16 g_Cxh[(size_t)Mrows*DOUT];
__device__ __nv_bfloat16 g_Cxl[(size_t)Mrows*DOUT];

// ======================= PTX helpers (compute_103 baseline only) ==========
__device__ __forceinline__ uint32_t smem_u32(const void* p) {
    uint32_t a;
    asm("{ .reg .u64 t; cvta.to.shared.u64 t, %1; cvt.u32.u64 %0, t; }" : "=r"(a) : "l"(p));
    return a;
}
__device__ __forceinline__ void cp16(uint32_t s, const void* g) {
    asm volatile("cp.async.cg.shared.global [%0], [%1], 16;" :: "r"(s), "l"(g));
}
#define CP_COMMIT() asm volatile("cp.async.commit_group;" ::: "memory")
#define CP_WAIT(n)  asm volatile("cp.async.wait_group %0;" :: "n"(n) : "memory")

__device__ __forceinline__ void ldsm_x4(uint32_t* r, uint32_t addr) {
    asm volatile("ldmatrix.sync.aligned.m8n8.x4.shared.b16 {%0,%1,%2,%3}, [%4];"
        : "=r"(r[0]), "=r"(r[1]), "=r"(r[2]), "=r"(r[3]) : "r"(addr));
}
__device__ __forceinline__ void mma16816(float* d, const uint32_t* a, const uint32_t* b) {
    asm volatile(
        "mma.sync.aligned.m16n8k16.row.col.f32.bf16.bf16.f32 "
        "{%0,%1,%2,%3}, {%4,%5,%6,%7}, {%8,%9}, {%0,%1,%2,%3};"
        : "+f"(d[0]), "+f"(d[1]), "+f"(d[2]), "+f"(d[3])
        : "r"(a[0]), "r"(a[1]), "r"(a[2]), "r"(a[3]), "r"(b[0]), "r"(b[1]));
}

// ======================= split / transpose-split ==========================
__global__ __launch_bounds__(256) void fsplit(const float* __restrict__ in,
                                              __nv_bfloat16* __restrict__ h,
                                              __nv_bfloat16* __restrict__ l, int n)
{
    int i = (blockIdx.x * 256 + threadIdx.x) * 4;
    if (i >= n) return;
    float4 v = *(const float4*)(in + i);
    __nv_bfloat16 h0 = __float2bfloat16(v.x), h1 = __float2bfloat16(v.y);
    __nv_bfloat16 h2 = __float2bfloat16(v.z), h3 = __float2bfloat16(v.w);
    __nv_bfloat16 l0 = __float2bfloat16(v.x - __bfloat162float(h0));
    __nv_bfloat16 l1 = __float2bfloat16(v.y - __bfloat162float(h1));
    __nv_bfloat16 l2 = __float2bfloat16(v.z - __bfloat162float(h2));
    __nv_bfloat16 l3 = __float2bfloat16(v.w - __bfloat162float(h3));
    *(__nv_bfloat162*)(h + i)     = __nv_bfloat162(h0, h1);
    *(__nv_bfloat162*)(h + i + 2) = __nv_bfloat162(h2, h3);
    *(__nv_bfloat162*)(l + i)     = __nv_bfloat162(l0, l1);
    *(__nv_bfloat162*)(l + i + 2) = __nv_bfloat162(l2, l3);
}

// W[K,N] fp32 -> Th/Tl[N,K] bf16 (transpose + split)
__global__ __launch_bounds__(256) void tsplit(const float* __restrict__ W,
                                              __nv_bfloat16* __restrict__ Th,
                                              __nv_bfloat16* __restrict__ Tl,
                                              int K, int N)
{
    __shared__ float t[32][33];
    const int n0 = blockIdx.x * 32, k0 = blockIdx.y * 32;
    const int tx = threadIdx.x, ty = threadIdx.y;  // (32, 8)
    #pragma unroll
    for (int r = 0; r < 4; r++)
        t[ty + r * 8][tx] = W[(size_t)(k0 + ty + r * 8) * N + n0 + tx];
    __syncthreads();
    #pragma unroll
    for (int r = 0; r < 4; r++) {
        int n = n0 + ty + r * 8, k = k0 + tx;
        float v = t[tx][ty + r * 8];
        __nv_bfloat16 h = __float2bfloat16(v);
        __nv_bfloat16 l = __float2bfloat16(v - __bfloat162float(h));
        Th[(size_t)n * K + k] = h;
        Tl[(size_t)n * K + k] = l;
    }
}

// ======================= HMMA split-bf16 GEMM ==============================
// C[M,N] = A[M,K] * B^T, A (hi/lo) [M,K], Bt (hi/lo) [N,K], K-major bf16.
// 128x128x32 block tile, 8 warps (2x4), 64x32 warp tile, 2-stage cp.async.
#define GBK   32
#define LDS   40                 // padded row length (elements)
#define TILEB (128 * LDS * 2)    // 10240 bytes per tile
#define STAGEB (4 * TILEB)       // Ah, Al, Bh, Bl
#define GEMM_SMEM (2 * STAGEB)   // 81920 bytes

__device__ __forceinline__ void load_stage(
    uint32_t smb, int stage,
    const __nv_bfloat16* __restrict__ pAh, const __nv_bfloat16* __restrict__ pAl,
    const __nv_bfloat16* __restrict__ pBh, const __nv_bfloat16* __restrict__ pBl,
    int K, int kc, int tid)
{
    const int row  = tid >> 1;
    const int half = (tid & 1) * 16;   // element offset within 32-elem row
    const uint32_t s = smb + stage * STAGEB + (uint32_t)(row * LDS + half) * 2;
    const size_t g = (size_t)row * K + kc + half;
    cp16(s + 0 * TILEB,      pAh + g);
    cp16(s + 0 * TILEB + 16, pAh + g + 8);
    cp16(s + 1 * TILEB,      pAl + g);
    cp16(s + 1 * TILEB + 16, pAl + g + 8);
    cp16(s + 2 * TILEB,      pBh + g);
    cp16(s + 2 * TILEB + 16, pBh + g + 8);
    cp16(s + 3 * TILEB,      pBl + g);
    cp16(s + 3 * TILEB + 16, pBl + g + 8);
}

__global__ __launch_bounds__(256, 1) void gemm_tc(
    const __nv_bfloat16* __restrict__ Ah, const __nv_bfloat16* __restrict__ Al,
    const __nv_bfloat16* __restrict__ Bh, const __nv_bfloat16* __restrict__ Bl,
    float* __restrict__ C, int M, int N, int K)
{
    extern __shared__ char sm[];
    const uint32_t smb = smem_u32(sm);
    const int tid  = threadIdx.x;
    const int wid  = tid >> 5, lane = tid & 31;
    const int wm   = wid >> 2;          // 0..1 -> 64 rows each
    const int wn   = wid & 3;           // 0..3 -> 32 cols each
    const int mb   = blockIdx.y * 128, nb = blockIdx.x * 128;

    const __nv_bfloat16* pAh = Ah + (size_t)mb * K;
    const __nv_bfloat16* pAl = Al + (size_t)mb * K;
    const __nv_bfloat16* pBh = Bh + (size_t)nb * K;
    const __nv_bfloat16* pBl = Bl + (size_t)nb * K;

    float acc[4][4][4];
    #pragma unroll
    for (int i = 0; i < 4; i++)
        #pragma unroll
        for (int j = 0; j < 4; j++)
            #pragma unroll
            for (int k = 0; k < 4; k++) acc[i][j][k] = 0.f;

    // per-lane ldmatrix base offsets (bytes), within a tile
    const uint32_t aoff = (uint32_t)((wm * 64 + (lane & 15)) * LDS + ((lane >> 4) * 8)) * 2;
    const uint32_t boff = (uint32_t)((wn * 32 + (lane & 7) + ((lane >> 4) << 3)) * LDS
                                     + (((lane >> 3) & 1) * 8)) * 2;

    const int NC = K / GBK;
    load_stage(smb, 0, pAh, pAl, pBh, pBl, K, 0, tid);
    CP_COMMIT();

    for (int c = 0; c < NC; c++) {
        if (c + 1 < NC) {
            load_stage(smb, (c + 1) & 1, pAh, pAl, pBh, pBl, K, (c + 1) * GBK, tid);
            CP_COMMIT();
            CP_WAIT(1);
        } else {
            CP_WAIT(0);
        }
        __syncthreads();

        const uint32_t st = smb + (c & 1) * STAGEB;
        #pragma unroll
        for (int ks = 0; ks < 2; ks++) {
            const uint32_t kb = ks * 32;   // 16 elements = 32 bytes
            uint32_t bh[8], bl[8];
            ldsm_x4(bh,     st + 2 * TILEB + boff + kb);
            ldsm_x4(bh + 4, st + 2 * TILEB + boff + 16 * LDS * 2 + kb);
            ldsm_x4(bl,     st + 3 * TILEB + boff + kb);
            ldsm_x4(bl + 4, st + 3 * TILEB + boff + 16 * LDS * 2 + kb);
            #pragma unroll
            for (int mf = 0; mf < 4; mf++) {
                uint32_t ah[4], al[4];
                ldsm_x4(ah, st + 0 * TILEB + aoff + mf * (16 * LDS * 2) + kb);
                ldsm_x4(al, st + 1 * TILEB + aoff + mf * (16 * LDS * 2) + kb);
                #pragma unroll
                for (int j = 0; j < 4; j++) {
                    const uint32_t* bhp = &bh[(j >> 1) * 4 + (j & 1) * 2];
                    const uint32_t* blp = &bl[(j >> 1) * 4 + (j & 1) * 2];
                    mma16816(acc[mf][j], ah, bhp);
                    mma16816(acc[mf][j], ah, blp);
                    mma16816(acc[mf][j], al, bhp);
                }
            }
        }
        __syncthreads();
    }

    // epilogue
    #pragma unroll
    for (int mf = 0; mf < 4; mf++) {
        const int m0 = mb + wm * 64 + mf * 16 + (lane >> 2);
        #pragma unroll
        for (int j = 0; j < 4; j++) {
            const int n0 = nb + wn * 32 + j * 8 + (lane & 3) * 2;
            *(float2*)(C + (size_t)m0 * N + n0)       = make_float2(acc[mf][j][0], acc[mf][j][1]);
            *(float2*)(C + (size_t)(m0 + 8) * N + n0) = make_float2(acc[mf][j][2], acc[mf][j][3]);
        }
    }
}

// ---------------- rmsnorm + rope for Q (one block per (b,s,h)) -------------
__global__ __launch_bounds__(128) void qnorm_rope(
    const float* __restrict__ QG, const float* __restrict__ w,
    const float* __restrict__ cosT, const float* __restrict__ sinT,
    float* __restrict__ Qo)
{
    const int s = blockIdx.x, h = blockIdx.y, b = blockIdx.z;
    const int d = threadIdx.x;
    const float* src = QG + (((size_t)(b * Sn + s) * Hn + h) * 2 * HD);
    float x = src[d];
    float ss = x * x;
    #pragma unroll
    for (int o = 16; o > 0; o >>= 1) ss += __shfl_xor_sync(0xffffffffu, ss, o);
    __shared__ float wsum[4];
    if ((d & 31) == 0) wsum[d >> 5] = ss;
    __syncthreads();
    float tot = wsum[0] + wsum[1] + wsum[2] + wsum[3];
    float inv = rsqrtf(tot * (1.0f / HD) + EPSf);
    float n = x * inv * (1.0f + w[d]);
    __shared__ float nb[HD];
    nb[d] = n;
    __syncthreads();
    float c  = cosT[(size_t)s * HD + d];
    float sn = sinT[(size_t)s * HD + d];
    float rot = (d < HD / 2) ? -nb[d + HD / 2] : nb[d - HD / 2];
    Qo[((size_t)(b * Hn + h) * Sn + s) * HD + d] = n * c + rot * sn;
}

// ---------------- rmsnorm + rope for K, plus V transpose -------------------
__global__ __launch_bounds__(128) void knorm_rope_vcopy(
    const float* __restrict__ Kraw, const float* __restrict__ Vraw,
    const float* __restrict__ w,
    const float* __restrict__ cosT, const float* __restrict__ sinT,
    float* __restrict__ Ko, float* __restrict__ Vo)
{
    const int s = blockIdx.x, g = blockIdx.y, b = blockIdx.z;
    const int d = threadIdx.x;
    const size_t src = ((size_t)(b * Sn + s) * Gn + g) * HD + d;
    float x = Kraw[src];
    float ss = x * x;
    #pragma unroll
    for (int o = 16; o > 0; o >>= 1) ss += __shfl_xor_sync(0xffffffffu, ss, o);
    __shared__ float wsum[4];
    if ((d & 31) == 0) wsum[d >> 5] = ss;
    __syncthreads();
    float tot = wsum[0] + wsum[1] + wsum[2] + wsum[3];
    float inv = rsqrtf(tot * (1.0f / HD) + EPSf);
    float n = x * inv * (1.0f + w[d]);
    __shared__ float nb[HD];
    nb[d] = n;
    __syncthreads();
    float c  = cosT[(size_t)s * HD + d];
    float sn = sinT[(size_t)s * HD + d];
    float rot = (d < HD / 2) ? -nb[d + HD / 2] : nb[d - HD / 2];
    const size_t dst = ((size_t)(b * Gn + g) * Sn + s) * HD + d;
    Ko[dst] = n * c + rot * sn;
    Vo[dst] = Vraw[src];
}

// ---------------- causal flash attention + sigmoid gate --------------------
#define BQ 64
#define BK 64
#define ATTN_SMEM_FLOATS (BQ*HD + HD*BK + BK*HD + BQ*BK + 3*BQ)

__global__ __launch_bounds__(256) void attn_kernel(
    const float* __restrict__ Q, const float* __restrict__ Kt,
    const float* __restrict__ Vt, const float* __restrict__ QG,
    float* __restrict__ Ctx)
{
    extern __shared__ float smf[];
    float* Qs  = smf;                   // [BQ][HD]
    float* Kst = Qs  + BQ * HD;         // [HD][BK]   (transposed)
    float* Vs  = Kst + HD * BK;         // [BK][HD]
    float* Ss  = Vs  + BK * HD;         // [BQ][BK]
    float* Ms  = Ss  + BQ * BK;
    float* Ls  = Ms  + BQ;
    float* Fs  = Ls  + BQ;

    const int qi = blockIdx.x, h = blockIdx.y, b = blockIdx.z;
    const int g  = h / GROUPn;
    const int tid = threadIdx.x;
    const int r0  = (tid / 16) * 4;
    const int kc0 = (tid % 16) * 4;
    const int c0  = (tid % 16) * 8;
    const float scale = 0.08838834764831845f;

    const float* Qbase = Q  + ((size_t)(b * Hn + h) * Sn + (size_t)qi * BQ) * HD;
    const float* Kbase = Kt + ((size_t)(b * Gn + g) * Sn) * HD;
    const float* Vbase = Vt + ((size_t)(b * Gn + g) * Sn) * HD;

    for (int i = tid * 4; i < BQ * HD; i += 1024)
        *(float4*)&Qs[i] = *(const float4*)&Qbase[i];
    if (tid < BQ) { Ms[tid] = -INFINITY; Ls[tid] = 0.f; }

    float acc[4][8];
    #pragma unroll
    for (int i = 0; i < 4; i++)
        #pragma unroll
        for (int j = 0; j < 8; j++) acc[i][j] = 0.f;

    const int ntiles = qi + 1;
    for (int t = 0; t < ntiles; ++t) {
        __syncthreads();
        const float* kp = Kbase + (size_t)t * BK * HD;
        const float* vp = Vbase + (size_t)t * BK * HD;
        for (int i = tid * 4; i < BK * HD; i += 1024) {
            int k = i / HD, d = i % HD;
            float4 kv = *(const float4*)&kp[i];
            Kst[(d + 0) * BK + k] = kv.x;
            Kst[(d + 1) * BK + k] = kv.y;
            Kst[(d + 2) * BK + k] = kv.z;
            Kst[(d + 3) * BK + k] = kv.w;
            *(float4*)&Vs[i] = *(const float4*)&vp[i];
        }
        __syncthreads();

        float sreg[4][4];
        #pragma unroll
        for (int i = 0; i < 4; i++)
            #pragma unroll
            for (int j = 0; j < 4; j++) sreg[i][j] = 0.f;
        #pragma unroll 4
        for (int d = 0; d < HD; ++d) {
            float4 k4 = *(const float4*)&Kst[d * BK + kc0];
            float kv[4] = {k4.x, k4.y, k4.z, k4.w};
            #pragma unroll
            for (int i = 0; i < 4; i++) {
                float qv = Qs[(r0 + i) * HD + d];
                #pragma unroll
                for (int j = 0; j < 4; j++) sreg[i][j] = fmaf(qv, kv[j], sreg[i][j]);
            }
        }
        const bool diag = (t == qi);
        #pragma unroll
        for (int i = 0; i < 4; i++)
            #pragma unroll
            for (int j = 0; j < 4; j++) {
                float v = sreg[i][j] * scale;
                if (diag && (kc0 + j > r0 + i)) v = -INFINITY;
                Ss[(r0 + i) * BK + kc0 + j] = v;
            }
        __syncthreads();

        if (tid < BQ) {
            const int r = tid;
            float m_old = Ms[r];
            float mt = m_old;
            #pragma unroll 8
            for (int k = 0; k < BK; ++k) mt = fmaxf(mt, Ss[r * BK + k]);
            float f = expf(m_old - mt);
            float l = Ls[r] * f;
            #pragma unroll 8
            for (int k = 0; k < BK; ++k) {
                float p = expf(Ss[r * BK + k] - mt);
                Ss[r * BK + k] = p;
                l += p;
            }
            Ms[r] = mt; Ls[r] = l; Fs[r] = f;
        }
        __syncthreads();

        #pragma unroll
        for (int i = 0; i < 4; i++) {
            float f = Fs[r0 + i];
            #pragma unroll
            for (int j = 0; j < 8; j++) acc[i][j] *= f;
        }
        #pragma unroll 2
        for (int kk = 0; kk < BK; ++kk) {
            float4 va = *(const float4*)&Vs[kk * HD + c0];
            float4 vb = *(const float4*)&Vs[kk * HD + c0 + 4];
            #pragma unroll
            for (int i = 0; i < 4; i++) {
                float p = Ss[(r0 + i) * BK + kk];
                acc[i][0] = fmaf(p, va.x, acc[i][0]);
                acc[i][1] = fmaf(p, va.y, acc[i][1]);
                acc[i][2] = fmaf(p, va.z, acc[i][2]);
                acc[i][3] = fmaf(p, va.w, acc[i][3]);
                acc[i][4] = fmaf(p, vb.x, acc[i][4]);
                acc[i][5] = fmaf(p, vb.y, acc[i][5]);
                acc[i][6] = fmaf(p, vb.z, acc[i][6]);
                acc[i][7] = fmaf(p, vb.w, acc[i][7]);
            }
        }
    }

    #pragma unroll
    for (int i = 0; i < 4; i++) {
        const int q = qi * BQ + r0 + i;
        const float invl = 1.0f / Ls[r0 + i];
        const float* gp = QG + (((size_t)(b * Sn + q) * Hn + h) * 2 * HD) + HD + c0;
        float* cp = Ctx + (size_t)(b * Sn + q) * DOUT + h * HD + c0;
        #pragma unroll
        for (int j = 0; j < 8; j++) {
            float gate = gp[j];
            float sig = 1.0f / (1.0f + expf(-gate));
            cp[j] = acc[i][j] * invl * sig;
        }
    }
}

// ---------------------------- launcher -------------------------------------
extern "C" void kernel_launch(void* const* d_in, const int* in_sizes, int n_in,
                              void* d_out, int out_size)
{
    const float* x    = (const float*)d_in[0];
    const float* Wq   = (const float*)d_in[1];
    const float* Wk   = (const float*)d_in[2];
    const float* Wv   = (const float*)d_in[3];
    const float* Wo   = (const float*)d_in[4];
    const float* qw   = (const float*)d_in[5];
    const float* kw   = (const float*)d_in[6];
    const float* cosT = (const float*)d_in[7];
    const float* sinT = (const float*)d_in[8];
    float* out = (float*)d_out;

    float *QG, *Kraw, *Vraw, *Qb, *Kb, *Vb, *Ctx;
    cudaGetSymbolAddress((void**)&QG,   g_QG);
    cudaGetSymbolAddress((void**)&Kraw, g_Kraw);
    cudaGetSymbolAddress((void**)&Vraw, g_Vraw);
    cudaGetSymbolAddress((void**)&Qb,   g_Q);
    cudaGetSymbolAddress((void**)&Kb,   g_K);
    cudaGetSymbolAddress((void**)&Vb,   g_V);
    cudaGetSymbolAddress((void**)&Ctx,  g_Ctx);

    __nv_bfloat16 *xh, *xl, *Wqh, *Wql, *Wkh, *Wkl, *Wvh, *Wvl, *Woh, *Wol, *Cxh, *Cxl;
    cudaGetSymbolAddress((void**)&xh,  g_xh);
    cudaGetSymbolAddress((void**)&xl,  g_xl);
    cudaGetSymbolAddress((void**)&Wqh, g_Wqh);
    cudaGetSymbolAddress((void**)&Wql, g_Wql);
    cudaGetSymbolAddress((void**)&Wkh, g_Wkh);
    cudaGetSymbolAddress((void**)&Wkl, g_Wkl);
    cudaGetSymbolAddress((void**)&Wvh, g_Wvh);
    cudaGetSymbolAddress((void**)&Wvl, g_Wvl);
    cudaGetSymbolAddress((void**)&Woh, g_Woh);
    cudaGetSymbolAddress((void**)&Wol, g_Wol);
    cudaGetSymbolAddress((void**)&Cxh, g_Cxh);
    cudaGetSymbolAddress((void**)&Cxl, g_Cxl);

    const size_t attn_smem = ATTN_SMEM_FLOATS * sizeof(float);
    cudaFuncSetAttribute(attn_kernel, cudaFuncAttributeMaxDynamicSharedMemorySize,
                         (int)attn_smem);
    cudaFuncSetAttribute(gemm_tc, cudaFuncAttributeMaxDynamicSharedMemorySize,
                         GEMM_SMEM);

    const int M = Mrows;  // 4096

    // split x
    fsplit<<<(M * DIN / 4 + 255) / 256, 256>>>(x, xh, xl, M * DIN);
    // transpose + split weights:  W[K,N] -> Wt[N,K]
    tsplit<<<dim3((2 * DOUT) / 32, DIN / 32), dim3(32, 8)>>>(Wq, Wqh, Wql, DIN, 2 * DOUT);
    tsplit<<<dim3((Gn * HD) / 32, DIN / 32), dim3(32, 8)>>>(Wk, Wkh, Wkl, DIN, Gn * HD);
    tsplit<<<dim3((Gn * HD) / 32, DIN / 32), dim3(32, 8)>>>(Wv, Wvh, Wvl, DIN, Gn * HD);
    tsplit<<<dim3(DIN / 32, DOUT / 32), dim3(32, 8)>>>(Wo, Woh, Wol, DOUT, DIN);

    // QKV projections (HMMA split-bf16)
    gemm_tc<<<dim3((2 * DOUT) / 128, M / 128), 256, GEMM_SMEM>>>(
        xh, xl, Wqh, Wql, QG, M, 2 * DOUT, DIN);
    gemm_tc<<<dim3((Gn * HD) / 128, M / 128), 256, GEMM_SMEM>>>(
        xh, xl, Wkh, Wkl, Kraw, M, Gn * HD, DIN);
    gemm_tc<<<dim3((Gn * HD) / 128, M / 128), 256, GEMM_SMEM>>>(
        xh, xl, Wvh, Wvl, Vraw, M, Gn * HD, DIN);

    // norm + rope (+ V transpose)
    qnorm_rope<<<dim3(Sn, Hn, Bn), 128>>>(QG, qw, cosT, sinT, Qb);
    knorm_rope_vcopy<<<dim3(Sn, Gn, Bn), 128>>>(Kraw, Vraw, kw, cosT, sinT, Kb, Vb);

    // causal attention + gate
    attn_kernel<<<dim3(Sn / BQ, Hn, Bn), 256, attn_smem>>>(Qb, Kb, Vb, QG, Ctx);

    // split ctx, then output projection (HMMA split-bf16)
    fsplit<<<(M * DOUT / 4 + 255) / 256, 256>>>(Ctx, Cxh, Cxl, M * DOUT);
    gemm_tc<<<dim3(DIN / 128, M / 128), 256, GEMM_SMEM>>>(
        Cxh, Cxl, Woh, Wol, out, M, DIN, DOUT);
}

// round 4
// speedup vs baseline: 2.8248x; 1.8474x over previous
#include <cuda_runtime.h>
#include <cuda_bf16.h>
#include <math.h>
#include <stdint.h>

#define Bn    2
#define Sn    2048
#define DIN   2048
#define Hn    16
#define Gn    4
#define HD    128
#define DOUT  2048
#define GROUPn 4          // H / G
#define EPSf  1e-6f
#define Mrows (Bn*Sn)     // 4096

// ---------------- scratch (device globals; no allocation allowed) ----------
__device__ float g_QG  [(size_t)Bn*Sn*Hn*2*HD];   // [b,s,h,2*HD]  (q | gate)
__device__ float g_Kraw[(size_t)Bn*Sn*Gn*HD];     // [b,s,g,HD]
__device__ float g_Vraw[(size_t)Bn*Sn*Gn*HD];     // [b,s,g,HD]
__device__ float g_Ctx [(size_t)Bn*Sn*DOUT];      // [b,s,h*HD]  gated context

// bf16 hi/lo attention operands
__device__ __nv_bfloat16 g_Qh[(size_t)Bn*Hn*Sn*HD];
__device__ __nv_bfloat16 g_Ql[(size_t)Bn*Hn*Sn*HD];
__device__ __nv_bfloat16 g_Kh[(size_t)Bn*Gn*Sn*HD];
__device__ __nv_bfloat16 g_Kl[(size_t)Bn*Gn*Sn*HD];
__device__ __nv_bfloat16 g_Vh[(size_t)Bn*Gn*Sn*HD];
__device__ __nv_bfloat16 g_Vl[(size_t)Bn*Gn*Sn*HD];

// bf16 split scratch for GEMMs
__device__ __nv_bfloat16 g_xh [(size_t)Mrows*DIN];
__device__ __nv_bfloat16 g_xl [(size_t)Mrows*DIN];
__device__ __nv_bfloat16 g_Wqh[(size_t)(2*DOUT)*DIN];
__device__ __nv_bfloat16 g_Wql[(size_t)(2*DOUT)*DIN];
__device__ __nv_bfloat16 g_Wkh[(size_t)(Gn*HD)*DIN];
__device__ __nv_bfloat16 g_Wkl[(size_t)(Gn*HD)*DIN];
__device__ __nv_bfloat16 g_Wvh[(size_t)(Gn*HD)*DIN];
__device__ __nv_bfloat16 g_Wvl[(size_t)(Gn*HD)*DIN];
__device__ __nv_bfloat16 g_Woh[(size_t)DIN*DOUT];
__device__ __nv_bfloat16 g_Wol[(size_t)DIN*DOUT];
__device__ __nv_bfloat16 g_Cxh[(size_t)Mrows*DOUT];
__device__ __nv_bfloat16 g_Cxl[(size_t)Mrows*DOUT];

// ======================= PTX helpers (compute_103 baseline only) ==========
__device__ __forceinline__ uint32_t smem_u32(const void* p) {
    uint32_t a;
    asm("{ .reg .u64 t; cvta.to.shared.u64 t, %1; cvt.u32.u64 %0, t; }" : "=r"(a) : "l"(p));
    return a;
}
__device__ __forceinline__ void cp16(uint32_t s, const void* g) {
    asm volatile("cp.async.cg.shared.global [%0], [%1], 16;" :: "r"(s), "l"(g));
}
#define CP_COMMIT() asm volatile("cp.async.commit_group;" ::: "memory")
#define CP_WAIT(n)  asm volatile("cp.async.wait_group %0;" :: "n"(n) : "memory")

__device__ __forceinline__ void ldsm_x4(uint32_t* r, uint32_t addr) {
    asm volatile("ldmatrix.sync.aligned.m8n8.x4.shared.b16 {%0,%1,%2,%3}, [%4];"
        : "=r"(r[0]), "=r"(r[1]), "=r"(r[2]), "=r"(r[3]) : "r"(addr));
}
__device__ __forceinline__ void ldsm_x4t(uint32_t* r, uint32_t addr) {
    asm volatile("ldmatrix.sync.aligned.m8n8.x4.trans.shared.b16 {%0,%1,%2,%3}, [%4];"
        : "=r"(r[0]), "=r"(r[1]), "=r"(r[2]), "=r"(r[3]) : "r"(addr));
}
__device__ __forceinline__ void mma16816(float* d, const uint32_t* a, const uint32_t* b) {
    asm volatile(
        "mma.sync.aligned.m16n8k16.row.col.f32.bf16.bf16.f32 "
        "{%0,%1,%2,%3}, {%4,%5,%6,%7}, {%8,%9}, {%0,%1,%2,%3};"
        : "+f"(d[0]), "+f"(d[1]), "+f"(d[2]), "+f"(d[3])
        : "r"(a[0]), "r"(a[1]), "r"(a[2]), "r"(a[3]), "r"(b[0]), "r"(b[1]));
}
__device__ __forceinline__ float ex2f(float x) {
    float r; asm("ex2.approx.f32 %0, %1;" : "=f"(r) : "f"(x)); return r;
}
__device__ __forceinline__ uint32_t packbf2(float lo, float hi) {
    uint32_t r; asm("cvt.rn.bf16x2.f32 %0, %1, %2;" : "=r"(r) : "f"(hi), "f"(lo)); return r;
}

// ======================= split / transpose-split ==========================
__global__ __launch_bounds__(256) void fsplit(const float* __restrict__ in,
                                              __nv_bfloat16* __restrict__ h,
                                              __nv_bfloat16* __restrict__ l, int n)
{
    int i = (blockIdx.x * 256 + threadIdx.x) * 4;
    if (i >= n) return;
    float4 v = *(const float4*)(in + i);
    __nv_bfloat16 h0 = __float2bfloat16(v.x), h1 = __float2bfloat16(v.y);
    __nv_bfloat16 h2 = __float2bfloat16(v.z), h3 = __float2bfloat16(v.w);
    __nv_bfloat16 l0 = __float2bfloat16(v.x - __bfloat162float(h0));
    __nv_bfloat16 l1 = __float2bfloat16(v.y - __bfloat162float(h1));
    __nv_bfloat16 l2 = __float2bfloat16(v.z - __bfloat162float(h2));
    __nv_bfloat16 l3 = __float2bfloat16(v.w - __bfloat162float(h3));
    *(__nv_bfloat162*)(h + i)     = __nv_bfloat162(h0, h1);
    *(__nv_bfloat162*)(h + i + 2) = __nv_bfloat162(h2, h3);
    *(__nv_bfloat162*)(l + i)     = __nv_bfloat162(l0, l1);
    *(__nv_bfloat162*)(l + i + 2) = __nv_bfloat162(l2, l3);
}

// W[K,N] fp32 -> Th/Tl[N,K] bf16 (transpose + split)
__global__ __launch_bounds__(256) void tsplit(const float* __restrict__ W,
                                              __nv_bfloat16* __restrict__ Th,
                                              __nv_bfloat16* __restrict__ Tl,
                                              int K, int N)
{
    __shared__ float t[32][33];
    const int n0 = blockIdx.x * 32, k0 = blockIdx.y * 32;
    const int tx = threadIdx.x, ty = threadIdx.y;  // (32, 8)
    #pragma unroll
    for (int r = 0; r < 4; r++)
        t[ty + r * 8][tx] = W[(size_t)(k0 + ty + r * 8) * N + n0 + tx];
    __syncthreads();
    #pragma unroll
    for (int r = 0; r < 4; r++) {
        int n = n0 + ty + r * 8, k = k0 + tx;
        float v = t[tx][ty + r * 8];
        __nv_bfloat16 h = __float2bfloat16(v);
        __nv_bfloat16 l = __float2bfloat16(v - __bfloat162float(h));
        Th[(size_t)n * K + k] = h;
        Tl[(size_t)n * K + k] = l;
    }
}

// ======================= HMMA split-bf16 GEMM ==============================
#define GBK   32
#define LDS   40
#define TILEB (128 * LDS * 2)
#define STAGEB (4 * TILEB)
#define GEMM_SMEM (2 * STAGEB)

__device__ __forceinline__ void load_stage(
    uint32_t smb, int stage,
    const __nv_bfloat16* __restrict__ pAh, const __nv_bfloat16* __restrict__ pAl,
    const __nv_bfloat16* __restrict__ pBh, const __nv_bfloat16* __restrict__ pBl,
    int K, int kc, int tid)
{
    const int row  = tid >> 1;
    const int half = (tid & 1) * 16;
    const uint32_t s = smb + stage * STAGEB + (uint32_t)(row * LDS + half) * 2;
    const size_t g = (size_t)row * K + kc + half;
    cp16(s + 0 * TILEB,      pAh + g);
    cp16(s + 0 * TILEB + 16, pAh + g + 8);
    cp16(s + 1 * TILEB,      pAl + g);
    cp16(s + 1 * TILEB + 16, pAl + g + 8);
    cp16(s + 2 * TILEB,      pBh + g);
    cp16(s + 2 * TILEB + 16, pBh + g + 8);
    cp16(s + 3 * TILEB,      pBl + g);
    cp16(s + 3 * TILEB + 16, pBl + g + 8);
}

__global__ __launch_bounds__(256, 1) void gemm_tc(
    const __nv_bfloat16* __restrict__ Ah, const __nv_bfloat16* __restrict__ Al,
    const __nv_bfloat16* __restrict__ Bh, const __nv_bfloat16* __restrict__ Bl,
    float* __restrict__ C, int M, int N, int K)
{
    extern __shared__ char sm[];
    const uint32_t smb = smem_u32(sm);
    const int tid  = threadIdx.x;
    const int wid  = tid >> 5, lane = tid & 31;
    const int wm   = wid >> 2;
    const int wn   = wid & 3;
    const int mb   = blockIdx.y * 128, nb = blockIdx.x * 128;

    const __nv_bfloat16* pAh = Ah + (size_t)mb * K;
    const __nv_bfloat16* pAl = Al + (size_t)mb * K;
    const __nv_bfloat16* pBh = Bh + (size_t)nb * K;
    const __nv_bfloat16* pBl = Bl + (size_t)nb * K;

    float acc[4][4][4];
    #pragma unroll
    for (int i = 0; i < 4; i++)
        #pragma unroll
        for (int j = 0; j < 4; j++)
            #pragma unroll
            for (int k = 0; k < 4; k++) acc[i][j][k] = 0.f;

    const uint32_t aoff = (uint32_t)((wm * 64 + (lane & 15)) * LDS + ((lane >> 4) * 8)) * 2;
    const uint32_t boff = (uint32_t)((wn * 32 + (lane & 7) + ((lane >> 4) << 3)) * LDS
                                     + (((lane >> 3) & 1) * 8)) * 2;

    const int NC = K / GBK;
    load_stage(smb, 0, pAh, pAl, pBh, pBl, K, 0, tid);
    CP_COMMIT();

    for (int c = 0; c < NC; c++) {
        if (c + 1 < NC) {
            load_stage(smb, (c + 1) & 1, pAh, pAl, pBh, pBl, K, (c + 1) * GBK, tid);
            CP_COMMIT();
            CP_WAIT(1);
        } else {
            CP_WAIT(0);
        }
        __syncthreads();

        const uint32_t st = smb + (c & 1) * STAGEB;
        #pragma unroll
        for (int ks = 0; ks < 2; ks++) {
            const uint32_t kb = ks * 32;
            uint32_t bh[8], bl[8];
            ldsm_x4(bh,     st + 2 * TILEB + boff + kb);
            ldsm_x4(bh + 4, st + 2 * TILEB + boff + 16 * LDS * 2 + kb);
            ldsm_x4(bl,     st + 3 * TILEB + boff + kb);
            ldsm_x4(bl + 4, st + 3 * TILEB + boff + 16 * LDS * 2 + kb);
            #pragma unroll
            for (int mf = 0; mf < 4; mf++) {
                uint32_t ah[4], al[4];
                ldsm_x4(ah, st + 0 * TILEB + aoff + mf * (16 * LDS * 2) + kb);
                ldsm_x4(al, st + 1 * TILEB + aoff + mf * (16 * LDS * 2) + kb);
                #pragma unroll
                for (int j = 0; j < 4; j++) {
                    const uint32_t* bhp = &bh[(j >> 1) * 4 + (j & 1) * 2];
                    const uint32_t* blp = &bl[(j >> 1) * 4 + (j & 1) * 2];
                    mma16816(acc[mf][j], ah, bhp);
                    mma16816(acc[mf][j], ah, blp);
                    mma16816(acc[mf][j], al, bhp);
                }
            }
        }
        __syncthreads();
    }

    #pragma unroll
    for (int mf = 0; mf < 4; mf++) {
        const int m0 = mb + wm * 64 + mf * 16 + (lane >> 2);
        #pragma unroll
        for (int j = 0; j < 4; j++) {
            const int n0 = nb + wn * 32 + j * 8 + (lane & 3) * 2;
            *(float2*)(C + (size_t)m0 * N + n0)       = make_float2(acc[mf][j][0], acc[mf][j][1]);
            *(float2*)(C + (size_t)(m0 + 8) * N + n0) = make_float2(acc[mf][j][2], acc[mf][j][3]);
        }
    }
}

// ---------------- rmsnorm + rope for Q -> bf16 hi/lo -----------------------
__global__ __launch_bounds__(128) void qnorm_rope(
    const float* __restrict__ QG, const float* __restrict__ w,
    const float* __restrict__ cosT, const float* __restrict__ sinT,
    __nv_bfloat16* __restrict__ Qh, __nv_bfloat16* __restrict__ Ql)
{
    const int s = blockIdx.x, h = blockIdx.y, b = blockIdx.z;
    const int d = threadIdx.x;
    const float* src = QG + (((size_t)(b * Sn + s) * Hn + h) * 2 * HD);
    float x = src[d];
    float ss = x * x;
    #pragma unroll
    for (int o = 16; o > 0; o >>= 1) ss += __shfl_xor_sync(0xffffffffu, ss, o);
    __shared__ float wsum[4];
    if ((d & 31) == 0) wsum[d >> 5] = ss;
    __syncthreads();
    float tot = wsum[0] + wsum[1] + wsum[2] + wsum[3];
    float inv = rsqrtf(tot * (1.0f / HD) + EPSf);
    float n = x * inv * (1.0f + w[d]);
    __shared__ float nb[HD];
    nb[d] = n;
    __syncthreads();
    float c  = cosT[(size_t)s * HD + d];
    float sn = sinT[(size_t)s * HD + d];
    float rot = (d < HD / 2) ? -nb[d + HD / 2] : nb[d - HD / 2];
    float y = n * c + rot * sn;
    __nv_bfloat16 hh = __float2bfloat16(y);
    const size_t dst = ((size_t)(b * Hn + h) * Sn + s) * HD + d;
    Qh[dst] = hh;
    Ql[dst] = __float2bfloat16(y - __bfloat162float(hh));
}

// ---------------- rmsnorm + rope for K -> hi/lo, plus V split --------------
__global__ __launch_bounds__(128) void knorm_rope_vsplit(
    const float* __restrict__ Kraw, const float* __restrict__ Vraw,
    const float* __restrict__ w,
    const float* __restrict__ cosT, const float* __restrict__ sinT,
    __nv_bfloat16* __restrict__ Kh, __nv_bfloat16* __restrict__ Kl,
    __nv_bfloat16* __restrict__ Vh, __nv_bfloat16* __restrict__ Vl)
{
    const int s = blockIdx.x, g = blockIdx.y, b = blockIdx.z;
    const int d = threadIdx.x;
    const size_t src = ((size_t)(b * Sn + s) * Gn + g) * HD + d;
    float x = Kraw[src];
    float ss = x * x;
    #pragma unroll
    for (int o = 16; o > 0; o >>= 1) ss += __shfl_xor_sync(0xffffffffu, ss, o);
    __shared__ float wsum[4];
    if ((d & 31) == 0) wsum[d >> 5] = ss;
    __syncthreads();
    float tot = wsum[0] + wsum[1] + wsum[2] + wsum[3];
    float inv = rsqrtf(tot * (1.0f / HD) + EPSf);
    float n = x * inv * (1.0f + w[d]);
    __shared__ float nb[HD];
    nb[d] = n;
    __syncthreads();
    float c  = cosT[(size_t)s * HD + d];
    float sn = sinT[(size_t)s * HD + d];
    float rot = (d < HD / 2) ? -nb[d + HD / 2] : nb[d - HD / 2];
    float y = n * c + rot * sn;
    const size_t dst = ((size_t)(b * Gn + g) * Sn + s) * HD + d;
    __nv_bfloat16 kh = __float2bfloat16(y);
    Kh[dst] = kh;
    Kl[dst] = __float2bfloat16(y - __bfloat162float(kh));
    float v = Vraw[src];
    __nv_bfloat16 vh = __float2bfloat16(v);
    Vh[dst] = vh;
    Vl[dst] = __float2bfloat16(v - __bfloat162float(vh));
}

// ================= HMMA causal flash attention + sigmoid gate ==============
// BQ=64 (4 warps x m16), BK=64, HD=128. 3-term split on both QK^T and PV.
#define AT_LDS  136                 // bf16 elems per smem row (128 + 8 pad)
#define QTILE   (64 * AT_LDS)       // elems per 64x128 tile
#define KVSTAGE (4 * QTILE)         // Kh,Kl,Vh,Vl
#define ATT_SMEM ((2 * QTILE + 2 * KVSTAGE) * 2)   // 174080 bytes
#define CSC 0.12751666806979654f    // (1/sqrt(128)) * log2(e)
#define NEGINF __int_as_float(0xff800000)

__device__ __forceinline__ void kv_load(
    uint32_t smb, int stage,
    const __nv_bfloat16* kh, const __nv_bfloat16* kl,
    const __nv_bfloat16* vh, const __nv_bfloat16* vl, int tid)
{
    const uint32_t base = smb + (2 * QTILE + stage * KVSTAGE) * 2;
    #pragma unroll
    for (int i = 0; i < 8; i++) {
        int u = tid + i * 128;          // 0..1023
        int row = u >> 4, c8 = (u & 15) * 8;
        uint32_t so = (uint32_t)(row * AT_LDS + c8) * 2;
        size_t go = (size_t)row * HD + c8;
        cp16(base + 0 * QTILE * 2 + so, kh + go);
        cp16(base + 1 * QTILE * 2 + so, kl + go);
        cp16(base + 2 * QTILE * 2 + so, vh + go);
        cp16(base + 3 * QTILE * 2 + so, vl + go);
    }
}

__global__ __launch_bounds__(128) void attn_mma(
    const __nv_bfloat16* __restrict__ Qh, const __nv_bfloat16* __restrict__ Ql,
    const __nv_bfloat16* __restrict__ Kh, const __nv_bfloat16* __restrict__ Kl,
    const __nv_bfloat16* __restrict__ Vh, const __nv_bfloat16* __restrict__ Vl,
    const float* __restrict__ QG, float* __restrict__ Ctx)
{
    extern __shared__ __nv_bfloat16 smem_bf[];
    const uint32_t smb = smem_u32(smem_bf);
    const int qi = blockIdx.x, h = blockIdx.y, b = blockIdx.z;
    const int g  = h / GROUPn;
    const int tid = threadIdx.x, lane = tid & 31, w = tid >> 5;

    const __nv_bfloat16* gQh = Qh + ((size_t)(b * Hn + h) * Sn + (size_t)qi * 64) * HD;
    const __nv_bfloat16* gQl = Ql + ((size_t)(b * Hn + h) * Sn + (size_t)qi * 64) * HD;
    const __nv_bfloat16* gKh = Kh + ((size_t)(b * Gn + g) * Sn) * HD;
    const __nv_bfloat16* gKl = Kl + ((size_t)(b * Gn + g) * Sn) * HD;
    const __nv_bfloat16* gVh = Vh + ((size_t)(b * Gn + g) * Sn) * HD;
    const __nv_bfloat16* gVl = Vl + ((size_t)(b * Gn + g) * Sn) * HD;

    // load Q hi/lo into smem
    #pragma unroll
    for (int i = 0; i < 8; i++) {
        int u = tid + i * 128;
        int row = u >> 4, c8 = (u & 15) * 8;
        *(uint4*)(smem_bf + row * AT_LDS + c8)         = *(const uint4*)(gQh + (size_t)row * HD + c8);
        *(uint4*)(smem_bf + QTILE + row * AT_LDS + c8) = *(const uint4*)(gQl + (size_t)row * HD + c8);
    }

    float m1 = NEGINF, m2 = NEGINF, l1 = 0.f, l2 = 0.f;
    float oacc[16][4];
    #pragma unroll
    for (int nf = 0; nf < 16; nf++)
        #pragma unroll
        for (int k = 0; k < 4; k++) oacc[nf][k] = 0.f;

    const int r1rel = w * 16 + (lane >> 2);
    const int r2rel = r1rel + 8;

    kv_load(smb, 0, gKh, gKl, gVh, gVl, tid);
    CP_COMMIT();

    for (int t = 0; t <= qi; t++) {
        if (t < qi) {
            kv_load(smb, (t + 1) & 1,
                    gKh + (size_t)(t + 1) * 64 * HD, gKl + (size_t)(t + 1) * 64 * HD,
                    gVh + (size_t)(t + 1) * 64 * HD, gVl + (size_t)(t + 1) * 64 * HD, tid);
            CP_COMMIT();
            CP_WAIT(1);
        } else {
            CP_WAIT(0);
        }
        __syncthreads();

        const uint32_t kb = smb + (2 * QTILE + (t & 1) * KVSTAGE) * 2;

        // ---- scores: S = Q K^T (3-term split) ----
        float sacc[8][4];
        #pragma unroll
        for (int j = 0; j < 8; j++)
            #pragma unroll
            for (int k = 0; k < 4; k++) sacc[j][k] = 0.f;

        #pragma unroll
        for (int kq = 0; kq < 8; kq++) {
            uint32_t ah[4], al[4];
            const uint32_t qaddr = smb +
                (uint32_t)((w * 16 + (lane & 15)) * AT_LDS + ((lane >> 4) << 3) + kq * 16) * 2;
            ldsm_x4(ah, qaddr);
            ldsm_x4(al, qaddr + QTILE * 2);
            #pragma unroll
            for (int n16 = 0; n16 < 4; n16++) {
                uint32_t bh[4], bl[4];
                const uint32_t kaddr = kb +
                    (uint32_t)((n16 * 16 + (lane & 7) + ((lane >> 4) << 3)) * AT_LDS
                               + (((lane >> 3) & 1) << 3) + kq * 16) * 2;
                ldsm_x4(bh, kaddr);
                ldsm_x4(bl, kaddr + QTILE * 2);
                mma16816(sacc[2 * n16],     ah, bh);     // hi*hi
                mma16816(sacc[2 * n16 + 1], ah, bh + 2);
                mma16816(sacc[2 * n16],     ah, bl);     // hi*lo
                mma16816(sacc[2 * n16 + 1], ah, bl + 2);
                mma16816(sacc[2 * n16],     al, bh);     // lo*hi
                mma16816(sacc[2 * n16 + 1], al, bh + 2);
            }
        }

        // ---- online softmax (log2 domain) ----
        const bool diag = (t == qi);
        float mt1 = m1, mt2 = m2;
        #pragma unroll
        for (int j = 0; j < 8; j++) {
            const int c0 = j * 8 + (lane & 3) * 2;
            #pragma unroll
            for (int k = 0; k < 4; k++) sacc[j][k] *= CSC;
            if (diag) {
                if (c0     > r1rel) sacc[j][0] = NEGINF;
                if (c0 + 1 > r1rel) sacc[j][1] = NEGINF;
                if (c0     > r2rel) sacc[j][2] = NEGINF;
                if (c0 + 1 > r2rel) sacc[j][3] = NEGINF;
            }
            mt1 = fmaxf(mt1, fmaxf(sacc[j][0], sacc[j][1]));
            mt2 = fmaxf(mt2, fmaxf(sacc[j][2], sacc[j][3]));
        }
        mt1 = fmaxf(mt1, __shfl_xor_sync(0xffffffffu, mt1, 1));
        mt1 = fmaxf(mt1, __shfl_xor_sync(0xffffffffu, mt1, 2));
        mt2 = fmaxf(mt2, __shfl_xor_sync(0xffffffffu, mt2, 1));
        mt2 = fmaxf(mt2, __shfl_xor_sync(0xffffffffu, mt2, 2));
        const float f1 = ex2f(m1 - mt1), f2 = ex2f(m2 - mt2);
        m1 = mt1; m2 = mt2;
        float s1 = 0.f, s2 = 0.f;
        #pragma unroll
        for (int j = 0; j < 8; j++) {
            sacc[j][0] = ex2f(sacc[j][0] - mt1);
            sacc[j][1] = ex2f(sacc[j][1] - mt1);
            sacc[j][2] = ex2f(sacc[j][2] - mt2);
            sacc[j][3] = ex2f(sacc[j][3] - mt2);
            s1 += sacc[j][0] + sacc[j][1];
            s2 += sacc[j][2] + sacc[j][3];
        }
        l1 = l1 * f1 + s1;
        l2 = l2 * f2 + s2;
        #pragma unroll
        for (int nf = 0; nf < 16; nf++) {
            oacc[nf][0] *= f1; oacc[nf][1] *= f1;
            oacc[nf][2] *= f2; oacc[nf][3] *= f2;
        }

        // ---- PV: out += P V (3-term split, P repacked in registers) ----
        #pragma unroll
        for (int kk = 0; kk < 4; kk++) {
            uint32_t aph[4], apl[4];
            #pragma unroll
            for (int half = 0; half < 2; half++) {
                const float p0 = sacc[2 * kk + half][0], p1 = sacc[2 * kk + half][1];
                const float p2 = sacc[2 * kk + half][2], p3 = sacc[2 * kk + half][3];
                const uint32_t h01 = packbf2(p0, p1);
                const uint32_t h23 = packbf2(p2, p3);
                aph[2 * half]     = h01;
                aph[2 * half + 1] = h23;
                apl[2 * half]     = packbf2(p0 - __uint_as_float(h01 << 16),
                                            p1 - __uint_as_float(h01 & 0xffff0000u));
                apl[2 * half + 1] = packbf2(p2 - __uint_as_float(h23 << 16),
                                            p3 - __uint_as_float(h23 & 0xffff0000u));
            }
            // NOTE: a-frag k-order: regs {r0,r1} = k 0..7 (frag 2kk), {r2,r3} = k 8..15 (frag 2kk+1)
            uint32_t a_h[4] = { aph[0], aph[1], aph[2], aph[3] };
            uint32_t a_l[4] = { apl[0], apl[1], apl[2], apl[3] };
            #pragma unroll
            for (int dc = 0; dc < 8; dc++) {
                uint32_t bvh[4], bvl[4];
                const uint32_t vaddr = kb + 2 * QTILE * 2 +
                    (uint32_t)((kk * 16 + (lane & 15)) * AT_LDS + dc * 16 + ((lane >> 4) << 3)) * 2;
                ldsm_x4t(bvh, vaddr);
                ldsm_x4t(bvl, vaddr + QTILE * 2);
                mma16816(oacc[2 * dc],     a_h, bvh);
                mma16816(oacc[2 * dc + 1], a_h, bvh + 2);
                mma16816(oacc[2 * dc],     a_h, bvl);
                mma16816(oacc[2 * dc + 1], a_h, bvl + 2);
                mma16816(oacc[2 * dc],     a_l, bvh);
                mma16816(oacc[2 * dc + 1], a_l, bvh + 2);
            }
        }
        __syncthreads();
    }

    // ---- epilogue: /l, * sigmoid(gate) ----
    l1 += __shfl_xor_sync(0xffffffffu, l1, 1);
    l1 += __shfl_xor_sync(0xffffffffu, l1, 2);
    l2 += __shfl_xor_sync(0xffffffffu, l2, 1);
    l2 += __shfl_xor_sync(0xffffffffu, l2, 2);
    const float inv1 = 1.0f / l1, inv2 = 1.0f / l2;
    const int q1 = qi * 64 + r1rel;
    const int q2 = q1 + 8;
    #pragma unroll
    for (int nf = 0; nf < 16; nf++) {
        const int dim = nf * 8 + (lane & 3) * 2;
        {
            const float2 gt = *(const float2*)(QG + (((size_t)(b * Sn + q1) * Hn + h) * 2 * HD) + HD + dim);
            const float s0 = 1.0f / (1.0f + expf(-gt.x));
            const float s1v = 1.0f / (1.0f + expf(-gt.y));
            *(float2*)(Ctx + (size_t)(b * Sn + q1) * DOUT + h * HD + dim) =
                make_float2(oacc[nf][0] * inv1 * s0, oacc[nf][1] * inv1 * s1v);
        }
        {
            const float2 gt = *(const float2*)(QG + (((size_t)(b * Sn + q2) * Hn + h) * 2 * HD) + HD + dim);
            const float s0 = 1.0f / (1.0f + expf(-gt.x));
            const float s1v = 1.0f / (1.0f + expf(-gt.y));
            *(float2*)(Ctx + (size_t)(b * Sn + q2) * DOUT + h * HD + dim) =
                make_float2(oacc[nf][2] * inv2 * s0, oacc[nf][3] * inv2 * s1v);
        }
    }
}

// ---------------------------- launcher -------------------------------------
extern "C" void kernel_launch(void* const* d_in, const int* in_sizes, int n_in,
                              void* d_out, int out_size)
{
    const float* x    = (const float*)d_in[0];
    const float* Wq   = (const float*)d_in[1];
    const float* Wk   = (const float*)d_in[2];
    const float* Wv   = (const float*)d_in[3];
    const float* Wo   = (const float*)d_in[4];
    const float* qw   = (const float*)d_in[5];
    const float* kw   = (const float*)d_in[6];
    const float* cosT = (const float*)d_in[7];
    const float* sinT = (const float*)d_in[8];
    float* out = (float*)d_out;

    float *QG, *Kraw, *Vraw, *Ctx;
    cudaGetSymbolAddress((void**)&QG,   g_QG);
    cudaGetSymbolAddress((void**)&Kraw, g_Kraw);
    cudaGetSymbolAddress((void**)&Vraw, g_Vraw);
    cudaGetSymbolAddress((void**)&Ctx,  g_Ctx);

    __nv_bfloat16 *Qhp, *Qlp, *Khp, *Klp, *Vhp, *Vlp;
    cudaGetSymbolAddress((void**)&Qhp, g_Qh);
    cudaGetSymbolAddress((void**)&Qlp, g_Ql);
    cudaGetSymbolAddress((void**)&Khp, g_Kh);
    cudaGetSymbolAddress((void**)&Klp, g_Kl);
    cudaGetSymbolAddress((void**)&Vhp, g_Vh);
    cudaGetSymbolAddress((void**)&Vlp, g_Vl);

    __nv_bfloat16 *xh, *xl, *Wqh, *Wql, *Wkh, *Wkl, *Wvh, *Wvl, *Woh, *Wol, *Cxh, *Cxl;
    cudaGetSymbolAddress((void**)&xh,  g_xh);
    cudaGetSymbolAddress((void**)&xl,  g_xl);
    cudaGetSymbolAddress((void**)&Wqh, g_Wqh);
    cudaGetSymbolAddress((void**)&Wql, g_Wql);
    cudaGetSymbolAddress((void**)&Wkh, g_Wkh);
    cudaGetSymbolAddress((void**)&Wkl, g_Wkl);
    cudaGetSymbolAddress((void**)&Wvh, g_Wvh);
    cudaGetSymbolAddress((void**)&Wvl, g_Wvl);
    cudaGetSymbolAddress((void**)&Woh, g_Woh);
    cudaGetSymbolAddress((void**)&Wol, g_Wol);
    cudaGetSymbolAddress((void**)&Cxh, g_Cxh);
    cudaGetSymbolAddress((void**)&Cxl, g_Cxl);

    cudaFuncSetAttribute(gemm_tc, cudaFuncAttributeMaxDynamicSharedMemorySize, GEMM_SMEM);
    cudaFuncSetAttribute(attn_mma, cudaFuncAttributeMaxDynamicSharedMemorySize, ATT_SMEM);

    const int M = Mrows;  // 4096

    // split x, transpose+split weights
    fsplit<<<(M * DIN / 4 + 255) / 256, 256>>>(x, xh, xl, M * DIN);
    tsplit<<<dim3((2 * DOUT) / 32, DIN / 32), dim3(32, 8)>>>(Wq, Wqh, Wql, DIN, 2 * DOUT);
    tsplit<<<dim3((Gn * HD) / 32, DIN / 32), dim3(32, 8)>>>(Wk, Wkh, Wkl, DIN, Gn * HD);
    tsplit<<<dim3((Gn * HD) / 32, DIN / 32), dim3(32, 8)>>>(Wv, Wvh, Wvl, DIN, Gn * HD);
    tsplit<<<dim3(DIN / 32, DOUT / 32), dim3(32, 8)>>>(Wo, Woh, Wol, DOUT, DIN);

    // QKV projections (HMMA split-bf16)
    gemm_tc<<<dim3((2 * DOUT) / 128, M / 128), 256, GEMM_SMEM>>>(
        xh, xl, Wqh, Wql, QG, M, 2 * DOUT, DIN);
    gemm_tc<<<dim3((Gn * HD) / 128, M / 128), 256, GEMM_SMEM>>>(
        xh, xl, Wkh, Wkl, Kraw, M, Gn * HD, DIN);
    gemm_tc<<<dim3((Gn * HD) / 128, M / 128), 256, GEMM_SMEM>>>(
        xh, xl, Wvh, Wvl, Vraw, M, Gn * HD, DIN);

    // norm + rope -> bf16 hi/lo
    qnorm_rope<<<dim3(Sn, Hn, Bn), 128>>>(QG, qw, cosT, sinT, Qhp, Qlp);
    knorm_rope_vsplit<<<dim3(Sn, Gn, Bn), 128>>>(Kraw, Vraw, kw, cosT, sinT,
                                                 Khp, Klp, Vhp, Vlp);

    // HMMA causal attention + gate
    attn_mma<<<dim3(Sn / 64, Hn, Bn), 128, ATT_SMEM>>>(
        Qhp, Qlp, Khp, Klp, Vhp, Vlp, QG, Ctx);

    // split ctx, output projection
    fsplit<<<(M * DOUT / 4 + 255) / 256, 256>>>(Ctx, Cxh, Cxl, M * DOUT);
    gemm_tc<<<dim3(DIN / 128, M / 128), 256, GEMM_SMEM>>>(
        Cxh, Cxl, Woh, Wol, out, M, DIN, DOUT);
}

// round 5
// speedup vs baseline: 3.0327x; 1.0736x over previous
#include <cuda_runtime.h>
#include <cuda_bf16.h>
#include <math.h>
#include <stdint.h>

#define Bn    2
#define Sn    2048
#define DIN   2048
#define Hn    16
#define Gn    4
#define HD    128
#define DOUT  2048
#define GROUPn 4          // H / G
#define EPSf  1e-6f
#define Mrows (Bn*Sn)     // 4096

// ---------------- scratch (device globals; no allocation allowed) ----------
__device__ float g_QG  [(size_t)Bn*Sn*Hn*2*HD];   // [b,s,h,2*HD]  (q | gate)
__device__ float g_Kraw[(size_t)Bn*Sn*Gn*HD];     // [b,s,g,HD]
__device__ float g_Vraw[(size_t)Bn*Sn*Gn*HD];     // [b,s,g,HD]
__device__ float g_Ctx [(size_t)Bn*Sn*DOUT];      // [b,s,h*HD]  gated context

// bf16 hi/lo attention operands
__device__ __nv_bfloat16 g_Qh[(size_t)Bn*Hn*Sn*HD];
__device__ __nv_bfloat16 g_Ql[(size_t)Bn*Hn*Sn*HD];
__device__ __nv_bfloat16 g_Kh[(size_t)Bn*Gn*Sn*HD];
__device__ __nv_bfloat16 g_Kl[(size_t)Bn*Gn*Sn*HD];
__device__ __nv_bfloat16 g_Vh[(size_t)Bn*Gn*Sn*HD];
__device__ __nv_bfloat16 g_Vl[(size_t)Bn*Gn*Sn*HD];

// bf16 split scratch for GEMMs
__device__ __nv_bfloat16 g_xh [(size_t)Mrows*DIN];
__device__ __nv_bfloat16 g_xl [(size_t)Mrows*DIN];
__device__ __nv_bfloat16 g_Wqh[(size_t)(2*DOUT)*DIN];
__device__ __nv_bfloat16 g_Wql[(size_t)(2*DOUT)*DIN];
__device__ __nv_bfloat16 g_Wkh[(size_t)(Gn*HD)*DIN];
__device__ __nv_bfloat16 g_Wkl[(size_t)(Gn*HD)*DIN];
__device__ __nv_bfloat16 g_Wvh[(size_t)(Gn*HD)*DIN];
__device__ __nv_bfloat16 g_Wvl[(size_t)(Gn*HD)*DIN];
__device__ __nv_bfloat16 g_Woh[(size_t)DIN*DOUT];
__device__ __nv_bfloat16 g_Wol[(size_t)DIN*DOUT];
__device__ __nv_bfloat16 g_Cxh[(size_t)Mrows*DOUT];
__device__ __nv_bfloat16 g_Cxl[(size_t)Mrows*DOUT];

// ======================= PTX helpers (compute_103 baseline only) ==========
__device__ __forceinline__ uint32_t smem_u32(const void* p) {
    uint32_t a;
    asm("{ .reg .u64 t; cvta.to.shared.u64 t, %1; cvt.u32.u64 %0, t; }" : "=r"(a) : "l"(p));
    return a;
}
__device__ __forceinline__ void cp16(uint32_t s, const void* g) {
    asm volatile("cp.async.cg.shared.global [%0], [%1], 16;" :: "r"(s), "l"(g));
}
#define CP_COMMIT() asm volatile("cp.async.commit_group;" ::: "memory")
#define CP_WAIT(n)  asm volatile("cp.async.wait_group %0;" :: "n"(n) : "memory")

__device__ __forceinline__ void ldsm_x4(uint32_t* r, uint32_t addr) {
    asm volatile("ldmatrix.sync.aligned.m8n8.x4.shared.b16 {%0,%1,%2,%3}, [%4];"
        : "=r"(r[0]), "=r"(r[1]), "=r"(r[2]), "=r"(r[3]) : "r"(addr));
}
__device__ __forceinline__ void ldsm_x4t(uint32_t* r, uint32_t addr) {
    asm volatile("ldmatrix.sync.aligned.m8n8.x4.trans.shared.b16 {%0,%1,%2,%3}, [%4];"
        : "=r"(r[0]), "=r"(r[1]), "=r"(r[2]), "=r"(r[3]) : "r"(addr));
}
__device__ __forceinline__ void mma16816(float* d, const uint32_t* a, const uint32_t* b) {
    asm volatile(
        "mma.sync.aligned.m16n8k16.row.col.f32.bf16.bf16.f32 "
        "{%0,%1,%2,%3}, {%4,%5,%6,%7}, {%8,%9}, {%0,%1,%2,%3};"
        : "+f"(d[0]), "+f"(d[1]), "+f"(d[2]), "+f"(d[3])
        : "r"(a[0]), "r"(a[1]), "r"(a[2]), "r"(a[3]), "r"(b[0]), "r"(b[1]));
}
__device__ __forceinline__ float ex2f(float x) {
    float r; asm("ex2.approx.f32 %0, %1;" : "=f"(r) : "f"(x)); return r;
}
__device__ __forceinline__ uint32_t packbf2(float lo, float hi) {
    uint32_t r; asm("cvt.rn.bf16x2.f32 %0, %1, %2;" : "=r"(r) : "f"(hi), "f"(lo)); return r;
}

// ======================= split / transpose-split ==========================
__global__ __launch_bounds__(256) void fsplit(const float* __restrict__ in,
                                              __nv_bfloat16* __restrict__ h,
                                              __nv_bfloat16* __restrict__ l, int n)
{
    int i = (blockIdx.x * 256 + threadIdx.x) * 4;
    if (i >= n) return;
    float4 v = *(const float4*)(in + i);
    __nv_bfloat16 h0 = __float2bfloat16(v.x), h1 = __float2bfloat16(v.y);
    __nv_bfloat16 h2 = __float2bfloat16(v.z), h3 = __float2bfloat16(v.w);
    __nv_bfloat16 l0 = __float2bfloat16(v.x - __bfloat162float(h0));
    __nv_bfloat16 l1 = __float2bfloat16(v.y - __bfloat162float(h1));
    __nv_bfloat16 l2 = __float2bfloat16(v.z - __bfloat162float(h2));
    __nv_bfloat16 l3 = __float2bfloat16(v.w - __bfloat162float(h3));
    *(__nv_bfloat162*)(h + i)     = __nv_bfloat162(h0, h1);
    *(__nv_bfloat162*)(h + i + 2) = __nv_bfloat162(h2, h3);
    *(__nv_bfloat162*)(l + i)     = __nv_bfloat162(l0, l1);
    *(__nv_bfloat162*)(l + i + 2) = __nv_bfloat162(l2, l3);
}

// W[K,N] fp32 -> Th/Tl[N,K] bf16 (transpose + split)
__global__ __launch_bounds__(256) void tsplit(const float* __restrict__ W,
                                              __nv_bfloat16* __restrict__ Th,
                                              __nv_bfloat16* __restrict__ Tl,
                                              int K, int N)
{
    __shared__ float t[32][33];
    const int n0 = blockIdx.x * 32, k0 = blockIdx.y * 32;
    const int tx = threadIdx.x, ty = threadIdx.y;  // (32, 8)
    #pragma unroll
    for (int r = 0; r < 4; r++)
        t[ty + r * 8][tx] = W[(size_t)(k0 + ty + r * 8) * N + n0 + tx];
    __syncthreads();
    #pragma unroll
    for (int r = 0; r < 4; r++) {
        int n = n0 + ty + r * 8, k = k0 + tx;
        float v = t[tx][ty + r * 8];
        __nv_bfloat16 h = __float2bfloat16(v);
        __nv_bfloat16 l = __float2bfloat16(v - __bfloat162float(h));
        Th[(size_t)n * K + k] = h;
        Tl[(size_t)n * K + k] = l;
    }
}

// ======================= HMMA split-bf16 GEMM (256x128 tile) ===============
// C[M,N] = A[M,K] * B^T, A (hi/lo) [M,K], Bt (hi/lo) [N,K], K-major bf16.
// Block: 256 threads (8 warps as 4m x 2n), warp tile 64x64, K-chunk 32.
#define GBK    32
#define LDS    40
#define ATILEB (256 * LDS * 2)   // 20480 B
#define BTILEB (128 * LDS * 2)   // 10240 B
#define STAGEB (2 * ATILEB + 2 * BTILEB)  // 61440 B
#define GEMM_SMEM (2 * STAGEB)            // 122880 B
#define OFF_AL  ATILEB
#define OFF_BH  (2 * ATILEB)
#define OFF_BL  (2 * ATILEB + BTILEB)

__device__ __forceinline__ void load_stage(
    uint32_t smb, int stage,
    const __nv_bfloat16* __restrict__ pAh, const __nv_bfloat16* __restrict__ pAl,
    const __nv_bfloat16* __restrict__ pBh, const __nv_bfloat16* __restrict__ pBl,
    int K, int kc, int tid)
{
    const uint32_t sb = smb + stage * STAGEB;
    // A: 256 rows x 32 cols -> 1024 cp16 units
    #pragma unroll
    for (int i = 0; i < 4; i++) {
        const int u = tid + i * 256;
        const int row = u >> 2, col = (u & 3) * 8;
        const uint32_t so = (uint32_t)(row * LDS + col) * 2;
        const size_t go = (size_t)row * K + kc + col;
        cp16(sb + so,          pAh + go);
        cp16(sb + OFF_AL + so, pAl + go);
    }
    // B: 128 rows x 32 cols -> 512 cp16 units
    #pragma unroll
    for (int i = 0; i < 2; i++) {
        const int u = tid + i * 256;
        const int row = u >> 2, col = (u & 3) * 8;
        const uint32_t so = (uint32_t)(row * LDS + col) * 2;
        const size_t go = (size_t)row * K + kc + col;
        cp16(sb + OFF_BH + so, pBh + go);
        cp16(sb + OFF_BL + so, pBl + go);
    }
}

__global__ __launch_bounds__(256, 1) void gemm_tc(
    const __nv_bfloat16* __restrict__ Ah, const __nv_bfloat16* __restrict__ Al,
    const __nv_bfloat16* __restrict__ Bh, const __nv_bfloat16* __restrict__ Bl,
    float* __restrict__ C, int M, int N, int K)
{
    extern __shared__ char sm[];
    const uint32_t smb = smem_u32(sm);
    const int tid  = threadIdx.x;
    const int wid  = tid >> 5, lane = tid & 31;
    const int wm   = wid & 3;           // 4 m-warps x 64 rows
    const int wn   = wid >> 2;          // 2 n-warps x 64 cols
    const int mb   = blockIdx.y * 256, nb = blockIdx.x * 128;

    const __nv_bfloat16* pAh = Ah + (size_t)mb * K;
    const __nv_bfloat16* pAl = Al + (size_t)mb * K;
    const __nv_bfloat16* pBh = Bh + (size_t)nb * K;
    const __nv_bfloat16* pBl = Bl + (size_t)nb * K;

    float acc[4][8][4];
    #pragma unroll
    for (int i = 0; i < 4; i++)
        #pragma unroll
        for (int j = 0; j < 8; j++)
            #pragma unroll
            for (int k = 0; k < 4; k++) acc[i][j][k] = 0.f;

    const uint32_t aoff = (uint32_t)((wm * 64 + (lane & 15)) * LDS + ((lane >> 4) * 8)) * 2;
    const uint32_t boff = (uint32_t)((wn * 64 + (lane & 7) + ((lane >> 4) << 3)) * LDS
                                     + (((lane >> 3) & 1) * 8)) * 2;

    const int NC = K / GBK;
    load_stage(smb, 0, pAh, pAl, pBh, pBl, K, 0, tid);
    CP_COMMIT();

    for (int c = 0; c < NC; c++) {
        if (c + 1 < NC) {
            load_stage(smb, (c + 1) & 1, pAh, pAl, pBh, pBl, K, (c + 1) * GBK, tid);
            CP_COMMIT();
            CP_WAIT(1);
        } else {
            CP_WAIT(0);
        }
        __syncthreads();

        const uint32_t st = smb + (c & 1) * STAGEB;
        #pragma unroll
        for (int ks = 0; ks < 2; ks++) {
            const uint32_t kb = ks * 32;
            uint32_t bh[16], bl[16];
            #pragma unroll
            for (int n16 = 0; n16 < 4; n16++) {
                ldsm_x4(bh + 4 * n16, st + OFF_BH + boff + n16 * (16 * LDS * 2) + kb);
                ldsm_x4(bl + 4 * n16, st + OFF_BL + boff + n16 * (16 * LDS * 2) + kb);
            }
            #pragma unroll
            for (int mf = 0; mf < 4; mf++) {
                uint32_t ah[4], al[4];
                ldsm_x4(ah, st + aoff + mf * (16 * LDS * 2) + kb);
                ldsm_x4(al, st + OFF_AL + aoff + mf * (16 * LDS * 2) + kb);
                #pragma unroll
                for (int nf = 0; nf < 8; nf++) {
                    const uint32_t* bhp = &bh[(nf >> 1) * 4 + (nf & 1) * 2];
                    const uint32_t* blp = &bl[(nf >> 1) * 4 + (nf & 1) * 2];
                    mma16816(acc[mf][nf], ah, bhp);
                    mma16816(acc[mf][nf], ah, blp);
                    mma16816(acc[mf][nf], al, bhp);
                }
            }
        }
        __syncthreads();
    }

    #pragma unroll
    for (int mf = 0; mf < 4; mf++) {
        const int m0 = mb + wm * 64 + mf * 16 + (lane >> 2);
        #pragma unroll
        for (int nf = 0; nf < 8; nf++) {
            const int n0 = nb + wn * 64 + nf * 8 + (lane & 3) * 2;
            *(float2*)(C + (size_t)m0 * N + n0)       = make_float2(acc[mf][nf][0], acc[mf][nf][1]);
            *(float2*)(C + (size_t)(m0 + 8) * N + n0) = make_float2(acc[mf][nf][2], acc[mf][nf][3]);
        }
    }
}

// ---------------- rmsnorm + rope for Q -> bf16 hi/lo -----------------------
__global__ __launch_bounds__(128) void qnorm_rope(
    const float* __restrict__ QG, const float* __restrict__ w,
    const float* __restrict__ cosT, const float* __restrict__ sinT,
    __nv_bfloat16* __restrict__ Qh, __nv_bfloat16* __restrict__ Ql)
{
    const int s = blockIdx.x, h = blockIdx.y, b = blockIdx.z;
    const int d = threadIdx.x;
    const float* src = QG + (((size_t)(b * Sn + s) * Hn + h) * 2 * HD);
    float x = src[d];
    float ss = x * x;
    #pragma unroll
    for (int o = 16; o > 0; o >>= 1) ss += __shfl_xor_sync(0xffffffffu, ss, o);
    __shared__ float wsum[4];
    if ((d & 31) == 0) wsum[d >> 5] = ss;
    __syncthreads();
    float tot = wsum[0] + wsum[1] + wsum[2] + wsum[3];
    float inv = rsqrtf(tot * (1.0f / HD) + EPSf);
    float n = x * inv * (1.0f + w[d]);
    __shared__ float nb[HD];
    nb[d] = n;
    __syncthreads();
    float c  = cosT[(size_t)s * HD + d];
    float sn = sinT[(size_t)s * HD + d];
    float rot = (d < HD / 2) ? -nb[d + HD / 2] : nb[d - HD / 2];
    float y = n * c + rot * sn;
    __nv_bfloat16 hh = __float2bfloat16(y);
    const size_t dst = ((size_t)(b * Hn + h) * Sn + s) * HD + d;
    Qh[dst] = hh;
    Ql[dst] = __float2bfloat16(y - __bfloat162float(hh));
}

// ---------------- rmsnorm + rope for K -> hi/lo, plus V split --------------
__global__ __launch_bounds__(128) void knorm_rope_vsplit(
    const float* __restrict__ Kraw, const float* __restrict__ Vraw,
    const float* __restrict__ w,
    const float* __restrict__ cosT, const float* __restrict__ sinT,
    __nv_bfloat16* __restrict__ Kh, __nv_bfloat16* __restrict__ Kl,
    __nv_bfloat16* __restrict__ Vh, __nv_bfloat16* __restrict__ Vl)
{
    const int s = blockIdx.x, g = blockIdx.y, b = blockIdx.z;
    const int d = threadIdx.x;
    const size_t src = ((size_t)(b * Sn + s) * Gn + g) * HD + d;
    float x = Kraw[src];
    float ss = x * x;
    #pragma unroll
    for (int o = 16; o > 0; o >>= 1) ss += __shfl_xor_sync(0xffffffffu, ss, o);
    __shared__ float wsum[4];
    if ((d & 31) == 0) wsum[d >> 5] = ss;
    __syncthreads();
    float tot = wsum[0] + wsum[1] + wsum[2] + wsum[3];
    float inv = rsqrtf(tot * (1.0f / HD) + EPSf);
    float n = x * inv * (1.0f + w[d]);
    __shared__ float nb[HD];
    nb[d] = n;
    __syncthreads();
    float c  = cosT[(size_t)s * HD + d];
    float sn = sinT[(size_t)s * HD + d];
    float rot = (d < HD / 2) ? -nb[d + HD / 2] : nb[d - HD / 2];
    float y = n * c + rot * sn;
    const size_t dst = ((size_t)(b * Gn + g) * Sn + s) * HD + d;
    __nv_bfloat16 kh = __float2bfloat16(y);
    Kh[dst] = kh;
    Kl[dst] = __float2bfloat16(y - __bfloat162float(kh));
    float v = Vraw[src];
    __nv_bfloat16 vh = __float2bfloat16(v);
    Vh[dst] = vh;
    Vl[dst] = __float2bfloat16(v - __bfloat162float(vh));
}

// ================= HMMA causal flash attention + sigmoid gate ==============
// BQ=128 (8 warps x m16), BK=64, HD=128. 3-term split on QK^T and PV.
#define AT_LDS  136
#define Q_ELE   (128 * AT_LDS)
#define KT_ELE  (64 * AT_LDS)
#define KVSTAGE_ELE (4 * KT_ELE)
#define ATT_SMEM ((2 * Q_ELE + 2 * KVSTAGE_ELE) * 2)   // 208896 bytes
#define CSC 0.12751666806979654f    // (1/sqrt(128)) * log2(e)
#define NEGINF __int_as_float(0xff800000)

__device__ __forceinline__ void kv_load(
    uint32_t smb, int stage,
    const __nv_bfloat16* kh, const __nv_bfloat16* kl,
    const __nv_bfloat16* vh, const __nv_bfloat16* vl, int tid)
{
    const uint32_t base = smb + (2 * Q_ELE + stage * KVSTAGE_ELE) * 2;
    #pragma unroll
    for (int i = 0; i < 4; i++) {
        int u = tid + i * 256;          // 0..1023
        int row = u >> 4, c8 = (u & 15) * 8;
        uint32_t so = (uint32_t)(row * AT_LDS + c8) * 2;
        size_t go = (size_t)row * HD + c8;
        cp16(base + 0 * KT_ELE * 2 + so, kh + go);
        cp16(base + 1 * KT_ELE * 2 + so, kl + go);
        cp16(base + 2 * KT_ELE * 2 + so, vh + go);
        cp16(base + 3 * KT_ELE * 2 + so, vl + go);
    }
}

__global__ __launch_bounds__(256, 1) void attn_mma(
    const __nv_bfloat16* __restrict__ Qh, const __nv_bfloat16* __restrict__ Ql,
    const __nv_bfloat16* __restrict__ Kh, const __nv_bfloat16* __restrict__ Kl,
    const __nv_bfloat16* __restrict__ Vh, const __nv_bfloat16* __restrict__ Vl,
    const float* __restrict__ QG, float* __restrict__ Ctx)
{
    extern __shared__ __nv_bfloat16 smem_bf[];
    const uint32_t smb = smem_u32(smem_bf);
    const int qi = blockIdx.x, h = blockIdx.y, b = blockIdx.z;
    const int g  = h / GROUPn;
    const int tid = threadIdx.x, lane = tid & 31, w = tid >> 5;

    const __nv_bfloat16* gQh = Qh + ((size_t)(b * Hn + h) * Sn + (size_t)qi * 128) * HD;
    const __nv_bfloat16* gQl = Ql + ((size_t)(b * Hn + h) * Sn + (size_t)qi * 128) * HD;
    const __nv_bfloat16* gKh = Kh + ((size_t)(b * Gn + g) * Sn) * HD;
    const __nv_bfloat16* gKl = Kl + ((size_t)(b * Gn + g) * Sn) * HD;
    const __nv_bfloat16* gVh = Vh + ((size_t)(b * Gn + g) * Sn) * HD;
    const __nv_bfloat16* gVl = Vl + ((size_t)(b * Gn + g) * Sn) * HD;

    // load Q hi/lo into smem (128 x 128)
    #pragma unroll
    for (int i = 0; i < 8; i++) {
        int u = tid + i * 256;
        int row = u >> 4, c8 = (u & 15) * 8;
        *(uint4*)(smem_bf + row * AT_LDS + c8)         = *(const uint4*)(gQh + (size_t)row * HD + c8);
        *(uint4*)(smem_bf + Q_ELE + row * AT_LDS + c8) = *(const uint4*)(gQl + (size_t)row * HD + c8);
    }

    float m1 = NEGINF, m2 = NEGINF, l1 = 0.f, l2 = 0.f;
    float oacc[16][4];
    #pragma unroll
    for (int nf = 0; nf < 16; nf++)
        #pragma unroll
        for (int k = 0; k < 4; k++) oacc[nf][k] = 0.f;

    const int r1rel = w * 16 + (lane >> 2);   // 0..127
    const int r2rel = r1rel + 8;
    const int r1g = qi * 128 + r1rel;
    const int r2g = r1g + 8;

    kv_load(smb, 0, gKh, gKl, gVh, gVl, tid);
    CP_COMMIT();

    const int ntiles = 2 * qi + 2;
    for (int t = 0; t < ntiles; t++) {
        if (t + 1 < ntiles) {
            kv_load(smb, (t + 1) & 1,
                    gKh + (size_t)(t + 1) * 64 * HD, gKl + (size_t)(t + 1) * 64 * HD,
                    gVh + (size_t)(t + 1) * 64 * HD, gVl + (size_t)(t + 1) * 64 * HD, tid);
            CP_COMMIT();
            CP_WAIT(1);
        } else {
            CP_WAIT(0);
        }
        __syncthreads();

        const uint32_t kb = smb + (2 * Q_ELE + (t & 1) * KVSTAGE_ELE) * 2;

        // ---- scores: S = Q K^T (3-term split) ----
        float sacc[8][4];
        #pragma unroll
        for (int j = 0; j < 8; j++)
            #pragma unroll
            for (int k = 0; k < 4; k++) sacc[j][k] = 0.f;

        #pragma unroll
        for (int kq = 0; kq < 8; kq++) {
            uint32_t ah[4], al[4];
            const uint32_t qaddr = smb +
                (uint32_t)((w * 16 + (lane & 15)) * AT_LDS + ((lane >> 4) << 3) + kq * 16) * 2;
            ldsm_x4(ah, qaddr);
            ldsm_x4(al, qaddr + Q_ELE * 2);
            #pragma unroll
            for (int n16 = 0; n16 < 4; n16++) {
                uint32_t bh[4], bl[4];
                const uint32_t kaddr = kb +
                    (uint32_t)((n16 * 16 + (lane & 7) + ((lane >> 4) << 3)) * AT_LDS
                               + (((lane >> 3) & 1) << 3) + kq * 16) * 2;
                ldsm_x4(bh, kaddr);
                ldsm_x4(bl, kaddr + KT_ELE * 2);
                mma16816(sacc[2 * n16],     ah, bh);
                mma16816(sacc[2 * n16 + 1], ah, bh + 2);
                mma16816(sacc[2 * n16],     ah, bl);
                mma16816(sacc[2 * n16 + 1], ah, bl + 2);
                mma16816(sacc[2 * n16],     al, bh);
                mma16816(sacc[2 * n16 + 1], al, bh + 2);
            }
        }

        // ---- online softmax (log2 domain) ----
        const bool needmask = (t >= 2 * qi);
        float mt1 = m1, mt2 = m2;
        #pragma unroll
        for (int j = 0; j < 8; j++) {
            const int c0 = t * 64 + j * 8 + (lane & 3) * 2;
            #pragma unroll
            for (int k = 0; k < 4; k++) sacc[j][k] *= CSC;
            if (needmask) {
                if (c0     > r1g) sacc[j][0] = NEGINF;
                if (c0 + 1 > r1g) sacc[j][1] = NEGINF;
                if (c0     > r2g) sacc[j][2] = NEGINF;
                if (c0 + 1 > r2g) sacc[j][3] = NEGINF;
            }
            mt1 = fmaxf(mt1, fmaxf(sacc[j][0], sacc[j][1]));
            mt2 = fmaxf(mt2, fmaxf(sacc[j][2], sacc[j][3]));
        }
        mt1 = fmaxf(mt1, __shfl_xor_sync(0xffffffffu, mt1, 1));
        mt1 = fmaxf(mt1, __shfl_xor_sync(0xffffffffu, mt1, 2));
        mt2 = fmaxf(mt2, __shfl_xor_sync(0xffffffffu, mt2, 1));
        mt2 = fmaxf(mt2, __shfl_xor_sync(0xffffffffu, mt2, 2));
        const float f1 = ex2f(m1 - mt1), f2 = ex2f(m2 - mt2);
        m1 = mt1; m2 = mt2;
        float s1 = 0.f, s2 = 0.f;
        #pragma unroll
        for (int j = 0; j < 8; j++) {
            sacc[j][0] = ex2f(sacc[j][0] - mt1);
            sacc[j][1] = ex2f(sacc[j][1] - mt1);
            sacc[j][2] = ex2f(sacc[j][2] - mt2);
            sacc[j][3] = ex2f(sacc[j][3] - mt2);
            s1 += sacc[j][0] + sacc[j][1];
            s2 += sacc[j][2] + sacc[j][3];
        }
        l1 = l1 * f1 + s1;
        l2 = l2 * f2 + s2;
        #pragma unroll
        for (int nf = 0; nf < 16; nf++) {
            oacc[nf][0] *= f1; oacc[nf][1] *= f1;
            oacc[nf][2] *= f2; oacc[nf][3] *= f2;
        }

        // ---- PV: out += P V (3-term split, P repacked in registers) ----
        #pragma unroll
        for (int kk = 0; kk < 4; kk++) {
            uint32_t aph[4], apl[4];
            #pragma unroll
            for (int half = 0; half < 2; half++) {
                const float p0 = sacc[2 * kk + half][0], p1 = sacc[2 * kk + half][1];
                const float p2 = sacc[2 * kk + half][2], p3 = sacc[2 * kk + half][3];
                const uint32_t h01 = packbf2(p0, p1);
                const uint32_t h23 = packbf2(p2, p3);
                aph[2 * half]     = h01;
                aph[2 * half + 1] = h23;
                apl[2 * half]     = packbf2(p0 - __uint_as_float(h01 << 16),
                                            p1 - __uint_as_float(h01 & 0xffff0000u));
                apl[2 * half + 1] = packbf2(p2 - __uint_as_float(h23 << 16),
                                            p3 - __uint_as_float(h23 & 0xffff0000u));
            }
            uint32_t a_h[4] = { aph[0], aph[1], aph[2], aph[3] };
            uint32_t a_l[4] = { apl[0], apl[1], apl[2], apl[3] };
            #pragma unroll
            for (int dc = 0; dc < 8; dc++) {
                uint32_t bvh[4], bvl[4];
                const uint32_t vaddr = kb + 2 * KT_ELE * 2 +
                    (uint32_t)((kk * 16 + (lane & 15)) * AT_LDS + dc * 16 + ((lane >> 4) << 3)) * 2;
                ldsm_x4t(bvh, vaddr);
                ldsm_x4t(bvl, vaddr + KT_ELE * 2);
                mma16816(oacc[2 * dc],     a_h, bvh);
                mma16816(oacc[2 * dc + 1], a_h, bvh + 2);
                mma16816(oacc[2 * dc],     a_h, bvl);
                mma16816(oacc[2 * dc + 1], a_h, bvl + 2);
                mma16816(oacc[2 * dc],     a_l, bvh);
                mma16816(oacc[2 * dc + 1], a_l, bvh + 2);
            }
        }
        __syncthreads();
    }

    // ---- epilogue: /l, * sigmoid(gate) ----
    l1 += __shfl_xor_sync(0xffffffffu, l1, 1);
    l1 += __shfl_xor_sync(0xffffffffu, l1, 2);
    l2 += __shfl_xor_sync(0xffffffffu, l2, 1);
    l2 += __shfl_xor_sync(0xffffffffu, l2, 2);
    const float inv1 = 1.0f / l1, inv2 = 1.0f / l2;
    #pragma unroll
    for (int nf = 0; nf < 16; nf++) {
        const int dim = nf * 8 + (lane & 3) * 2;
        {
            const float2 gt = *(const float2*)(QG + (((size_t)(b * Sn + r1g) * Hn + h) * 2 * HD) + HD + dim);
            const float s0 = 1.0f / (1.0f + expf(-gt.x));
            const float s1v = 1.0f / (1.0f + expf(-gt.y));
            *(float2*)(Ctx + (size_t)(b * Sn + r1g) * DOUT + h * HD + dim) =
                make_float2(oacc[nf][0] * inv1 * s0, oacc[nf][1] * inv1 * s1v);
        }
        {
            const float2 gt = *(const float2*)(QG + (((size_t)(b * Sn + r2g) * Hn + h) * 2 * HD) + HD + dim);
            const float s0 = 1.0f / (1.0f + expf(-gt.x));
            const float s1v = 1.0f / (1.0f + expf(-gt.y));
            *(float2*)(Ctx + (size_t)(b * Sn + r2g) * DOUT + h * HD + dim) =
                make_float2(oacc[nf][2] * inv2 * s0, oacc[nf][3] * inv2 * s1v);
        }
    }
}

// ---------------------------- launcher -------------------------------------
extern "C" void kernel_launch(void* const* d_in, const int* in_sizes, int n_in,
                              void* d_out, int out_size)
{
    const float* x    = (const float*)d_in[0];
    const float* Wq   = (const float*)d_in[1];
    const float* Wk   = (const float*)d_in[2];
    const float* Wv   = (const float*)d_in[3];
    const float* Wo   = (const float*)d_in[4];
    const float* qw   = (const float*)d_in[5];
    const float* kw   = (const float*)d_in[6];
    const float* cosT = (const float*)d_in[7];
    const float* sinT = (const float*)d_in[8];
    float* out = (float*)d_out;

    float *QG, *Kraw, *Vraw, *Ctx;
    cudaGetSymbolAddress((void**)&QG,   g_QG);
    cudaGetSymbolAddress((void**)&Kraw, g_Kraw);
    cudaGetSymbolAddress((void**)&Vraw, g_Vraw);
    cudaGetSymbolAddress((void**)&Ctx,  g_Ctx);

    __nv_bfloat16 *Qhp, *Qlp, *Khp, *Klp, *Vhp, *Vlp;
    cudaGetSymbolAddress((void**)&Qhp, g_Qh);
    cudaGetSymbolAddress((void**)&Qlp, g_Ql);
    cudaGetSymbolAddress((void**)&Khp, g_Kh);
    cudaGetSymbolAddress((void**)&Klp, g_Kl);
    cudaGetSymbolAddress((void**)&Vhp, g_Vh);
    cudaGetSymbolAddress((void**)&Vlp, g_Vl);

    __nv_bfloat16 *xh, *xl, *Wqh, *Wql, *Wkh, *Wkl, *Wvh, *Wvl, *Woh, *Wol, *Cxh, *Cxl;
    cudaGetSymbolAddress((void**)&xh,  g_xh);
    cudaGetSymbolAddress((void**)&xl,  g_xl);
    cudaGetSymbolAddress((void**)&Wqh, g_Wqh);
    cudaGetSymbolAddress((void**)&Wql, g_Wql);
    cudaGetSymbolAddress((void**)&Wkh, g_Wkh);
    cudaGetSymbolAddress((void**)&Wkl, g_Wkl);
    cudaGetSymbolAddress((void**)&Wvh, g_Wvh);
    cudaGetSymbolAddress((void**)&Wvl, g_Wvl);
    cudaGetSymbolAddress((void**)&Woh, g_Woh);
    cudaGetSymbolAddress((void**)&Wol, g_Wol);
    cudaGetSymbolAddress((void**)&Cxh, g_Cxh);
    cudaGetSymbolAddress((void**)&Cxl, g_Cxl);

    cudaFuncSetAttribute(gemm_tc, cudaFuncAttributeMaxDynamicSharedMemorySize, GEMM_SMEM);
    cudaFuncSetAttribute(attn_mma, cudaFuncAttributeMaxDynamicSharedMemorySize, ATT_SMEM);

    const int M = Mrows;  // 4096

    // split x, transpose+split weights
    fsplit<<<(M * DIN / 4 + 255) / 256, 256>>>(x, xh, xl, M * DIN);
    tsplit<<<dim3((2 * DOUT) / 32, DIN / 32), dim3(32, 8)>>>(Wq, Wqh, Wql, DIN, 2 * DOUT);
    tsplit<<<dim3((Gn * HD) / 32, DIN / 32), dim3(32, 8)>>>(Wk, Wkh, Wkl, DIN, Gn * HD);
    tsplit<<<dim3((Gn * HD) / 32, DIN / 32), dim3(32, 8)>>>(Wv, Wvh, Wvl, DIN, Gn * HD);
    tsplit<<<dim3(DIN / 32, DOUT / 32), dim3(32, 8)>>>(Wo, Woh, Wol, DOUT, DIN);

    // QKV projections (HMMA split-bf16, 256x128 tiles)
    gemm_tc<<<dim3((2 * DOUT) / 128, M / 256), 256, GEMM_SMEM>>>(
        xh, xl, Wqh, Wql, QG, M, 2 * DOUT, DIN);
    gemm_tc<<<dim3((Gn * HD) / 128, M / 256), 256, GEMM_SMEM>>>(
        xh, xl, Wkh, Wkl, Kraw, M, Gn * HD, DIN);
    gemm_tc<<<dim3((Gn * HD) / 128, M / 256), 256, GEMM_SMEM>>>(
        xh, xl, Wvh, Wvl, Vraw, M, Gn * HD, DIN);

    // norm + rope -> bf16 hi/lo
    qnorm_rope<<<dim3(Sn, Hn, Bn), 128>>>(QG, qw, cosT, sinT, Qhp, Qlp);
    knorm_rope_vsplit<<<dim3(Sn, Gn, Bn), 128>>>(Kraw, Vraw, kw, cosT, sinT,
                                                 Khp, Klp, Vhp, Vlp);

    // HMMA causal attention + gate (BQ=128)
    attn_mma<<<dim3(Sn / 128, Hn, Bn), 256, ATT_SMEM>>>(
        Qhp, Qlp, Khp, Klp, Vhp, Vlp, QG, Ctx);

    // split ctx, output projection
    fsplit<<<(M * DOUT / 4 + 255) / 256, 256>>>(Ctx, Cxh, Cxl, M * DOUT);
    gemm_tc<<<dim3(DIN / 128, M / 256), 256, GEMM_SMEM>>>(
        Cxh, Cxl, Woh, Wol, out, M, DIN, DOUT);
}